// round 3
// baseline (speedup 1.0000x reference)
#include <cuda_runtime.h>
#include <cuda_bf16.h>
#include <math.h>

#define NROWS 65536
#define DIN   480
#define H0D   512
#define H1D   256
#define H2D   128
#define GDIM  384

// ---------------- scratch (device globals; no allocation) ----------------
__device__ float gY0[(size_t)NROWS * 128];      // y0 / sqrt(128)
__device__ float gY1[(size_t)3 * NROWS * 64];   // [m][row][u]  y1*inv*nw1/sqrt(64)
__device__ float gY2[(size_t)5 * NROWS * 32];   // [m][row][u]  y2*inv*nw2/sqrt(32)
__device__ float gS [(size_t)NROWS * H0D];      // silu(h0[:512]) / sqrt(512)
__device__ float gG [(size_t)NROWS * GDIM];     // sigmoid(h0[512:896])
__device__ float gZ1[(size_t)3 * NROWS * H1D];  // [m][row][w]  h1*g / sqrt(256)
__device__ float gZ2[(size_t)5 * NROWS * H2D];  // [m][row][w]  h2*g / sqrt(128)

// ---------------- f32x2 helpers ----------------
__device__ __forceinline__ unsigned long long pack2(float v) {
    unsigned long long r;
    asm("mov.b64 %0, {%1, %1};" : "=l"(r) : "r"(__float_as_uint(v)));
    return r;
}
__device__ __forceinline__ void fma2(unsigned long long& d,
                                     unsigned long long a,
                                     unsigned long long b) {
    asm("fma.rn.f32x2 %0, %1, %2, %3;" : "=l"(d) : "l"(a), "l"(b), "l"(d));
}
__device__ __forceinline__ float2 unpack2(unsigned long long v) {
    float2 r;
    asm("mov.b64 {%0, %1}, %2;" : "=f"(r.x), "=f"(r.y) : "l"(v));
    return r;
}
__device__ __forceinline__ float sigmf(float v) {
    return 1.0f / (1.0f + __expf(-v));
}

// ---------------- kernel 1: norms ----------------
// 8 warps/block, one warp per row.
__global__ void __launch_bounds__(256) norm_kernel(
    const float* __restrict__ x,  const float* __restrict__ nw0,
    const float* __restrict__ nb0, const float* __restrict__ nw1,
    const float* __restrict__ nw2)
{
    const int warp = threadIdx.x >> 5;
    const int lane = threadIdx.x & 31;
    const int row  = blockIdx.x * 8 + warp;
    const float* xr = x + (size_t)row * DIN;

    // x0 stats (128 floats, 1 float4/lane)
    float4 v0 = ((const float4*)xr)[lane];
    float s = v0.x + v0.y + v0.z + v0.w;
    float q = v0.x*v0.x + v0.y*v0.y + v0.z*v0.z + v0.w*v0.w;
#pragma unroll
    for (int o = 16; o; o >>= 1) {
        s += __shfl_xor_sync(0xffffffffu, s, o);
        q += __shfl_xor_sync(0xffffffffu, q, o);
    }
    const float mu   = s * (1.0f / 128.0f);
    const float var  = q * (1.0f / 128.0f) - mu * mu;
    const float rstd = rsqrtf(var + 1e-8f);

    // x1/x2 sum of squares (352 floats = 88 float4, split at f4 index 48)
    float ss1 = 0.f, ss2 = 0.f;
    const float4* xr2 = (const float4*)(xr + 128);
#pragma unroll
    for (int j = lane; j < 88; j += 32) {
        float4 v = xr2[j];
        float d = v.x*v.x + v.y*v.y + v.z*v.z + v.w*v.w;
        if (j < 48) ss1 += d; else ss2 += d;
    }
#pragma unroll
    for (int o = 16; o; o >>= 1) {
        ss1 += __shfl_xor_sync(0xffffffffu, ss1, o);
        ss2 += __shfl_xor_sync(0xffffffffu, ss2, o);
    }
    const float inv = rsqrtf(0.5f * (ss1 * (1.f/192.f) + ss2 * (1.f/160.f)) + 1e-8f);

    // y0 write (scaled by 1/sqrt(128))
    const float invS0 = 0.08838834764831845f;
    float4 w = ((const float4*)nw0)[lane];
    float4 b = ((const float4*)nb0)[lane];
    float4 y;
    y.x = ((v0.x - mu) * rstd * w.x + b.x) * invS0;
    y.y = ((v0.y - mu) * rstd * w.y + b.y) * invS0;
    y.z = ((v0.z - mu) * rstd * w.z + b.z) * invS0;
    y.w = ((v0.w - mu) * rstd * w.w + b.w) * invS0;
    ((float4*)(gY0 + (size_t)row * 128))[lane] = y;

    // y1: [m][row][u], scaled by 1/sqrt(64)
#pragma unroll
    for (int t = 0; t < 2; ++t) {
        int u = lane + t * 32;
        float c = inv * nw1[u] * 0.125f;
#pragma unroll
        for (int m = 0; m < 3; ++m)
            gY1[((size_t)m * NROWS + row) * 64 + u] = xr[128 + 3*u + m] * c;
    }
    // y2: [m][row][u], scaled by 1/sqrt(32)
    {
        int u = lane;
        float c = inv * nw2[u] * 0.17677669529663689f;
#pragma unroll
        for (int m = 0; m < 5; ++m)
            gY2[((size_t)m * NROWS + row) * 32 + u] = xr[320 + 5*u + m] * c;
    }
}

// ---------------- templated GEMM + epilogue ----------------
// C[128 x BP] tile = A[128 x Kd] @ B[Kd x Pd] slab, FFMA2 inner product.
// EPI: 0 = h0 -> silu->gS / sigmoid->gG     (A=gY0, B=W0, bias=b0)
//      1 = z1 = (Y1m@W1) * g * invT1 -> gZ1 (A=gY1[m], B=W1)
//      2 = z2 = (Y2m@W2) * g * invT2 -> gZ2 (A=gY2[m], B=W2)
//      3 = out0 = x + ta*(gS@V0 + c0)       (A=gS,  B=V0, bias=c0)
//      4 = out1 = x + ta*(gZ1m@V1)          (A=gZ1[m], B=V1)
//      5 = out2 = x + ta*(gZ2m@V2)          (A=gZ2[m], B=V2)
template<int Kd, int Pd, int BP, int TC, int EPI>
__global__ void __launch_bounds__(256) gemm_kernel(
    const float* __restrict__ B, const float* __restrict__ bias,
    const float* __restrict__ X, const float* __restrict__ alphap,
    float* __restrict__ Out)
{
    constexpr int BK = 32;
    constexpr int CP = TC / 2;

    __shared__ __align__(16) float sA[128][BK + 1];
    __shared__ __align__(16) float sB[BK][BP];

    const int tid  = threadIdx.x;
    const int trow = tid >> 4;   // 0..15 -> rows trow*8 .. +7
    const int tcol = tid & 15;   // 0..15 -> cols tcol*TC .. +TC-1
    const int rowBase = blockIdx.x * 128;
    const int pb      = blockIdx.y * BP;
    const int m       = blockIdx.z;

    const float* A =
        (EPI == 0) ? gY0 : (EPI == 1) ? gY1 : (EPI == 2) ? gY2 :
        (EPI == 3) ? gS  : (EPI == 4) ? gZ1 : gZ2;
    const float* Am = A + (size_t)m * NROWS * Kd;

    unsigned long long acc[8][CP];
#pragma unroll
    for (int i = 0; i < 8; ++i)
#pragma unroll
        for (int c = 0; c < CP; ++c) acc[i][c] = 0ull;

    for (int kt = 0; kt < Kd; kt += BK) {
        // A tile: 128 x 32, float4 along k, row-major smem (stride 33)
        {
            const int k4 = tid & 7;
            const int r0 = tid >> 3;
#pragma unroll
            for (int pass = 0; pass < 4; ++pass) {
                int r = r0 + pass * 32;
                float4 v = *(const float4*)(Am + (size_t)(rowBase + r) * Kd + kt + 4 * k4);
                sA[r][4*k4 + 0] = v.x; sA[r][4*k4 + 1] = v.y;
                sA[r][4*k4 + 2] = v.z; sA[r][4*k4 + 3] = v.w;
            }
        }
        // B tile: 32 x BP
        {
            constexpr int NB = (BK * BP / 4) / 256;
#pragma unroll
            for (int t = 0; t < NB; ++t) {
                int idx = tid + t * 256;
                int kk  = idx / (BP / 4);
                int p4  = idx % (BP / 4);
                *(float4*)&sB[kk][4 * p4] =
                    *(const float4*)(B + (size_t)(kt + kk) * Pd + pb + 4 * p4);
            }
        }
        __syncthreads();

#pragma unroll 8
        for (int k = 0; k < BK; ++k) {
            unsigned long long bj[CP];
#pragma unroll
            for (int c = 0; c < CP; ++c)
                bj[c] = *(const unsigned long long*)&sB[k][tcol * TC + 2 * c];
#pragma unroll
            for (int i = 0; i < 8; ++i) {
                unsigned long long a2 = pack2(sA[trow * 8 + i][k]);
#pragma unroll
                for (int c = 0; c < CP; ++c) fma2(acc[i][c], a2, bj[c]);
            }
        }
        __syncthreads();
    }

    // ---------------- epilogue ----------------
    const float ta = (EPI >= 3) ? tanhf(alphap[0]) : 0.0f;
#pragma unroll
    for (int i = 0; i < 8; ++i) {
        const int row = rowBase + trow * 8 + i;
#pragma unroll
        for (int c = 0; c < CP; ++c) {
            float2 v = unpack2(acc[i][c]);
            const int p0 = pb + tcol * TC + 2 * c;

            if (EPI == 0) {
                float ha = v.x + bias[p0];
                float hb = v.y + bias[p0 + 1];
                if (p0 < H0D) {  // block-uniform: pb multiple of 128
                    const float invT0 = 0.04419417382415922f;
                    gS[(size_t)row * H0D + p0]     = ha * sigmf(ha) * invT0;
                    gS[(size_t)row * H0D + p0 + 1] = hb * sigmf(hb) * invT0;
                } else {
                    gG[(size_t)row * GDIM + p0 - H0D]     = sigmf(ha);
                    gG[(size_t)row * GDIM + p0 - H0D + 1] = sigmf(hb);
                }
            } else if (EPI == 1) {
                const float invT1 = 0.0625f;
                float g0 = gG[(size_t)row * GDIM + p0];
                float g1 = gG[(size_t)row * GDIM + p0 + 1];
                gZ1[((size_t)m * NROWS + row) * H1D + p0]     = v.x * g0 * invT1;
                gZ1[((size_t)m * NROWS + row) * H1D + p0 + 1] = v.y * g1 * invT1;
            } else if (EPI == 2) {
                const float invT2 = 0.08838834764831845f;
                float g0 = gG[(size_t)row * GDIM + H1D + p0];
                float g1 = gG[(size_t)row * GDIM + H1D + p0 + 1];
                gZ2[((size_t)m * NROWS + row) * H2D + p0]     = v.x * g0 * invT2;
                gZ2[((size_t)m * NROWS + row) * H2D + p0 + 1] = v.y * g1 * invT2;
            } else if (EPI == 3) {
                int o = row * DIN + p0;
                Out[o]     = X[o]     + ta * (v.x + bias[p0]);
                Out[o + 1] = X[o + 1] + ta * (v.y + bias[p0 + 1]);
            } else if (EPI == 4) {
                int o = row * DIN + 128 + 3 * p0 + m;
                Out[o]     = X[o]     + ta * v.x;
                Out[o + 3] = X[o + 3] + ta * v.y;
            } else {
                int o = row * DIN + 320 + 5 * p0 + m;
                Out[o]     = X[o]     + ta * v.x;
                Out[o + 5] = X[o + 5] + ta * v.y;
            }
        }
    }
}

// ---------------- launch ----------------
extern "C" void kernel_launch(void* const* d_in, const int* in_sizes, int n_in,
                              void* d_out, int out_size) {
    const float* x     = (const float*)d_in[0];
    const float* nw0   = (const float*)d_in[1];
    const float* nb0   = (const float*)d_in[2];
    const float* nw1   = (const float*)d_in[3];
    const float* nw2   = (const float*)d_in[4];
    const float* W0    = (const float*)d_in[5];
    const float* b0    = (const float*)d_in[6];
    const float* W1    = (const float*)d_in[7];
    const float* W2    = (const float*)d_in[8];
    const float* V0    = (const float*)d_in[9];
    const float* c0    = (const float*)d_in[10];
    const float* V1    = (const float*)d_in[11];
    const float* V2    = (const float*)d_in[12];
    const float* alpha = (const float*)d_in[13];
    float* out = (float*)d_out;

    norm_kernel<<<NROWS / 8, 256>>>(x, nw0, nb0, nw1, nw2);

    // stage 1: h0 -> s,g   (Kd=128, Pd=896)
    gemm_kernel<128, 896, 128, 8, 0><<<dim3(512, 7, 1), 256>>>(W0, b0, nullptr, nullptr, nullptr);
    // z1 = (Y1m @ W1) * g  (Kd=64, Pd=256), m = blockIdx.z
    gemm_kernel< 64, 256, 128, 8, 1><<<dim3(512, 2, 3), 256>>>(W1, nullptr, nullptr, nullptr, nullptr);
    // z2 = (Y2m @ W2) * g  (Kd=32, Pd=128)
    gemm_kernel< 32, 128, 128, 8, 2><<<dim3(512, 1, 5), 256>>>(W2, nullptr, nullptr, nullptr, nullptr);

    // stage 2: down-projections + residual
    gemm_kernel<512, 128, 128, 8, 3><<<dim3(512, 1, 1), 256>>>(V0, c0, x, alpha, out);
    gemm_kernel<256,  64,  64, 4, 4><<<dim3(512, 1, 3), 256>>>(V1, nullptr, x, alpha, out);
    gemm_kernel<128,  32,  32, 2, 5><<<dim3(512, 1, 5), 256>>>(V2, nullptr, x, alpha, out);
}

// round 5
// speedup vs baseline: 1.8122x; 1.8122x over previous
#include <cuda_runtime.h>
#include <cuda_bf16.h>
#include <math.h>
#include <cstdint>

#define NROWS 65536
#define DIN   480
#define H0D   512
#define GDIM  384

// ================= scratch (device globals; no allocation) =================
__device__ __nv_bfloat16 gY0b[(size_t)NROWS * 128];       // y0 /sqrt(128)
__device__ __nv_bfloat16 gY1b[(size_t)3 * NROWS * 64];    // [m][row][64]
__device__ __nv_bfloat16 gY2b[(size_t)5 * NROWS * 64];    // [m][row][64] (k 32..63 zero)
__device__ __nv_bfloat16 gSb [(size_t)NROWS * 512];       // silu(h0)/sqrt(512)
__device__ float         gG  [(size_t)NROWS * GDIM];      // sigmoid gates (fp32)
__device__ __nv_bfloat16 gZ1b[(size_t)3 * NROWS * 256];   // z1/sqrt(256)
__device__ __nv_bfloat16 gZ2b[(size_t)5 * NROWS * 128];   // z2/sqrt(128)
// transposed bf16 weights  Wt[p][k]
__device__ __nv_bfloat16 gWt0[(size_t)896 * 128];
__device__ __nv_bfloat16 gWt1[(size_t)256 * 64];
__device__ __nv_bfloat16 gWt2[(size_t)128 * 64];          // k 32..63 zero
__device__ __nv_bfloat16 gVt0[(size_t)128 * 512];
__device__ __nv_bfloat16 gVt1[(size_t)64 * 256];
__device__ __nv_bfloat16 gVt2[(size_t)32 * 128];

// ================= helpers =================
__device__ __forceinline__ uint32_t smem_to_u32(const void* p) {
    uint32_t a;
    asm("{ .reg .u64 t; cvta.to.shared.u64 t, %1; cvt.u32.u64 %0, t; }" : "=r"(a) : "l"(p));
    return a;
}
#define SWZ(b) ((b) ^ (((b) >> 3) & 0x70))

__device__ __forceinline__ void ldsm_x4(uint32_t* r, uint32_t addr) {
    asm volatile("ldmatrix.sync.aligned.m8n8.x4.shared.b16 {%0,%1,%2,%3}, [%4];"
        : "=r"(r[0]), "=r"(r[1]), "=r"(r[2]), "=r"(r[3]) : "r"(addr));
}
__device__ __forceinline__ void ldsm_x2(uint32_t* r, uint32_t addr) {
    asm volatile("ldmatrix.sync.aligned.m8n8.x2.shared.b16 {%0,%1}, [%2];"
        : "=r"(r[0]), "=r"(r[1]) : "r"(addr));
}
__device__ __forceinline__ void mma16816(float* d, const uint32_t* a, const uint32_t* b) {
    asm volatile(
        "mma.sync.aligned.m16n8k16.row.col.f32.bf16.bf16.f32 "
        "{%0,%1,%2,%3}, {%4,%5,%6,%7}, {%8,%9}, {%0,%1,%2,%3};"
        : "+f"(d[0]), "+f"(d[1]), "+f"(d[2]), "+f"(d[3])
        : "r"(a[0]), "r"(a[1]), "r"(a[2]), "r"(a[3]), "r"(b[0]), "r"(b[1]));
}
__device__ __forceinline__ float sigmf(float v) { return 1.0f / (1.0f + __expf(-v)); }

// ================= kernel 0: weight convert+transpose =================
__global__ void __launch_bounds__(256) convert_w(
    const float* __restrict__ W0, const float* __restrict__ W1, const float* __restrict__ W2,
    const float* __restrict__ V0, const float* __restrict__ V1, const float* __restrict__ V2)
{
    int i = blockIdx.x * 256 + threadIdx.x;
    if (i < 114688) {                       // Wt0[896][128] <- W0[128][896]
        int p = i / 128, k = i % 128;
        gWt0[i] = __float2bfloat16(W0[k * 896 + p]);
    } else if ((i -= 114688) < 16384) {     // Wt1[256][64] <- W1[64][256]
        int p = i / 64, k = i % 64;
        gWt1[i] = __float2bfloat16(W1[k * 256 + p]);
    } else if ((i -= 16384) < 8192) {       // Wt2[128][64] <- W2[32][128], pad
        int p = i / 64, k = i % 64;
        gWt2[i] = (k < 32) ? __float2bfloat16(W2[k * 128 + p]) : __float2bfloat16(0.f);
    } else if ((i -= 8192) < 65536) {       // Vt0[128][512] <- V0[512][128]
        int p = i / 512, k = i % 512;
        gVt0[i] = __float2bfloat16(V0[k * 128 + p]);
    } else if ((i -= 65536) < 16384) {      // Vt1[64][256] <- V1[256][64]
        int p = i / 256, k = i % 256;
        gVt1[i] = __float2bfloat16(V1[k * 64 + p]);
    } else if ((i -= 16384) < 4096) {       // Vt2[32][128] <- V2[128][32]
        int p = i / 128, k = i % 128;
        gVt2[i] = __float2bfloat16(V2[k * 32 + p]);
    }
}

// ================= kernel 1: norms (one warp per row) =================
__global__ void __launch_bounds__(256) norm_kernel(
    const float* __restrict__ x,  const float* __restrict__ nw0,
    const float* __restrict__ nb0, const float* __restrict__ nw1,
    const float* __restrict__ nw2)
{
    const int warp = threadIdx.x >> 5;
    const int lane = threadIdx.x & 31;
    const int row  = blockIdx.x * 8 + warp;
    const float* xr = x + (size_t)row * DIN;

    float4 v0 = ((const float4*)xr)[lane];
    float s = v0.x + v0.y + v0.z + v0.w;
    float q = v0.x*v0.x + v0.y*v0.y + v0.z*v0.z + v0.w*v0.w;
#pragma unroll
    for (int o = 16; o; o >>= 1) {
        s += __shfl_xor_sync(0xffffffffu, s, o);
        q += __shfl_xor_sync(0xffffffffu, q, o);
    }
    const float mu   = s * (1.0f / 128.0f);
    const float rstd = rsqrtf(q * (1.0f / 128.0f) - mu * mu + 1e-8f);

    float ss1 = 0.f, ss2 = 0.f;
    const float4* xr2 = (const float4*)(xr + 128);
#pragma unroll
    for (int j = lane; j < 88; j += 32) {
        float4 v = xr2[j];
        float d = v.x*v.x + v.y*v.y + v.z*v.z + v.w*v.w;
        if (j < 48) ss1 += d; else ss2 += d;
    }
#pragma unroll
    for (int o = 16; o; o >>= 1) {
        ss1 += __shfl_xor_sync(0xffffffffu, ss1, o);
        ss2 += __shfl_xor_sync(0xffffffffu, ss2, o);
    }
    const float inv = rsqrtf(0.5f * (ss1 * (1.f/192.f) + ss2 * (1.f/160.f)) + 1e-8f);

    const float invS0 = 0.08838834764831845f;
    float4 w = ((const float4*)nw0)[lane];
    float4 b = ((const float4*)nb0)[lane];
    __nv_bfloat16* y0 = gY0b + (size_t)row * 128 + lane * 4;
    y0[0] = __float2bfloat16(((v0.x - mu) * rstd * w.x + b.x) * invS0);
    y0[1] = __float2bfloat16(((v0.y - mu) * rstd * w.y + b.y) * invS0);
    y0[2] = __float2bfloat16(((v0.z - mu) * rstd * w.z + b.z) * invS0);
    y0[3] = __float2bfloat16(((v0.w - mu) * rstd * w.w + b.w) * invS0);

#pragma unroll
    for (int t = 0; t < 2; ++t) {
        int u = lane + t * 32;
        float c = inv * nw1[u] * 0.125f;
#pragma unroll
        for (int m = 0; m < 3; ++m)
            gY1b[((size_t)m * NROWS + row) * 64 + u] = __float2bfloat16(xr[128 + 3*u + m] * c);
    }
    {
        int u = lane;
        float c = inv * nw2[u] * 0.17677669529663689f;
#pragma unroll
        for (int m = 0; m < 5; ++m) {
            size_t base = ((size_t)m * NROWS + row) * 64;
            gY2b[base + u]      = __float2bfloat16(xr[320 + 5*u + m] * c);
            gY2b[base + u + 32] = __float2bfloat16(0.f);
        }
    }
}

// ================= HMMA GEMM + epilogue =================
// C[128 x NT] = A[128 x KdA] @ Wt[NT x KdA]^T   (bf16 in, fp32 acc)
// 8 warps: 2(m) x 4(n); warp tile 64 x (NT/4). K chunked by 64.
// EPI: 0 h0->silu/sigmoid  1 z1  2 z2  3 out0  4 out1  5 out2
template<int KdA, int NT, int EPI>
__global__ void __launch_bounds__(256, 2) mma_kernel(
    const float* __restrict__ bias, const float* __restrict__ X,
    const float* __restrict__ alphap, float* __restrict__ Out)
{
    constexpr int NCH  = KdA / 64;
    constexpr int WT_N = NT / 4;       // 32 / 16 / 8
    constexpr int NI   = WT_N / 8;     // 4 / 2 / 1
    constexpr int MI   = 4;            // warp tile m = 64

    __shared__ __align__(16) __nv_bfloat16 sA[128 * 64];
    __shared__ __align__(16) __nv_bfloat16 sB[NT * 64];
    const uint32_t sa = smem_to_u32(sA);
    const uint32_t sbB = smem_to_u32(sB);

    const int tid  = threadIdx.x;
    const int wid  = tid >> 5;
    const int lane = tid & 31;
    const int wm   = wid >> 2;         // 0..1
    const int wn   = wid & 3;          // 0..3
    const int rowBase = blockIdx.x * 128;
    const int pb      = blockIdx.y * NT;
    const int m       = blockIdx.z;

    const __nv_bfloat16* gA =
        (EPI == 0) ? gY0b : (EPI == 1) ? gY1b : (EPI == 2) ? gY2b :
        (EPI == 3) ? gSb  : (EPI == 4) ? gZ1b : gZ2b;
    const __nv_bfloat16* gBw =
        (EPI == 0) ? gWt0 : (EPI == 1) ? gWt1 : (EPI == 2) ? gWt2 :
        (EPI == 3) ? gVt0 : (EPI == 4) ? gVt1 : gVt2;
    const __nv_bfloat16* Am = gA + (size_t)m * NROWS * KdA;

    float acc[MI][NI][4];
#pragma unroll
    for (int i = 0; i < MI; ++i)
#pragma unroll
        for (int j = 0; j < NI; ++j)
#pragma unroll
            for (int r = 0; r < 4; ++r) acc[i][j][r] = 0.f;

    // precomputed ldmatrix lane addressing
    const int a_rowoff = (lane & 7) + ((lane >> 3) & 1) * 8;
    const int a_khalf  = lane >> 4;          // 0/1
    const int laneb    = lane & 15;
    const int b_rowoff = laneb & 7;
    const int b_khalf  = laneb >> 3;         // 0/1

#pragma unroll 1
    for (int ch = 0; ch < NCH; ++ch) {
        const int kt = ch * 64;
        // A tile: 128 rows x 64 bf16 (128B rows, swizzled)
#pragma unroll
        for (int t = 0; t < 4; ++t) {
            int idx = tid + t * 256;
            int r = idx >> 3, v = idx & 7;
            uint4 d = *(const uint4*)(Am + (size_t)(rowBase + r) * KdA + kt + v * 8);
            *(uint4*)((char*)sA + SWZ(r * 128 + v * 16)) = d;
        }
        // B tile: NT rows x 64 bf16
#pragma unroll
        for (int t = 0; t < NT / 32; ++t) {
            int idx = tid + t * 256;
            int r = idx >> 3, v = idx & 7;
            uint4 d = *(const uint4*)(gBw + (size_t)(pb + r) * KdA + kt + v * 8);
            *(uint4*)((char*)sB + SWZ(r * 128 + v * 16)) = d;
        }
        __syncthreads();

#pragma unroll
        for (int ks = 0; ks < 4; ++ks) {
            const int kbyte = ks * 32;
            uint32_t af[MI][4], bf[NI][2];
#pragma unroll
            for (int mi = 0; mi < MI; ++mi) {
                int r = wm * 64 + mi * 16 + a_rowoff;
                ldsm_x4(af[mi], sa + SWZ(r * 128 + kbyte + a_khalf * 16));
            }
#pragma unroll
            for (int ni = 0; ni < NI; ++ni) {
                int r = wn * WT_N + ni * 8 + b_rowoff;
                ldsm_x2(bf[ni], sbB + SWZ(r * 128 + kbyte + b_khalf * 16));
            }
#pragma unroll
            for (int mi = 0; mi < MI; ++mi)
#pragma unroll
                for (int ni = 0; ni < NI; ++ni)
                    mma16816(acc[mi][ni], af[mi], bf[ni]);
        }
        __syncthreads();
    }

    // ---------------- epilogue ----------------
    const float ta = (EPI >= 3) ? tanhf(alphap[0]) : 0.0f;
#pragma unroll
    for (int mi = 0; mi < MI; ++mi) {
        const int row0 = rowBase + wm * 64 + mi * 16 + (lane >> 2);
#pragma unroll
        for (int ni = 0; ni < NI; ++ni) {
            const int p0 = pb + wn * WT_N + ni * 8 + (lane & 3) * 2;
#pragma unroll
            for (int r = 0; r < 4; ++r) {
                const int row = row0 + (r >> 1) * 8;
                const int p   = p0 + (r & 1);
                const float v = acc[mi][ni][r];
                if (EPI == 0) {
                    float h = v + bias[p];
                    if (p < H0D) {   // uniform per block (pb multiple of 128)
                        gSb[(size_t)row * 512 + p] =
                            __float2bfloat16(h * sigmf(h) * 0.04419417382415922f);
                    } else {
                        gG[(size_t)row * GDIM + p - H0D] = sigmf(h);
                    }
                } else if (EPI == 1) {
                    float g = gG[(size_t)row * GDIM + p];
                    gZ1b[((size_t)m * NROWS + row) * 256 + p] =
                        __float2bfloat16(v * g * 0.0625f);
                } else if (EPI == 2) {
                    float g = gG[(size_t)row * GDIM + 256 + p];
                    gZ2b[((size_t)m * NROWS + row) * 128 + p] =
                        __float2bfloat16(v * g * 0.08838834764831845f);
                } else if (EPI == 3) {
                    int o = row * DIN + p;
                    Out[o] = X[o] + ta * (v + bias[p]);
                } else if (EPI == 4) {
                    int o = row * DIN + 128 + 3 * p + m;
                    Out[o] = X[o] + ta * v;
                } else {
                    int o = row * DIN + 320 + 5 * p + m;
                    Out[o] = X[o] + ta * v;
                }
            }
        }
    }
}

// ================= launch =================
extern "C" void kernel_launch(void* const* d_in, const int* in_sizes, int n_in,
                              void* d_out, int out_size) {
    const float* x     = (const float*)d_in[0];
    const float* nw0   = (const float*)d_in[1];
    const float* nb0   = (const float*)d_in[2];
    const float* nw1   = (const float*)d_in[3];
    const float* nw2   = (const float*)d_in[4];
    const float* W0    = (const float*)d_in[5];
    const float* b0    = (const float*)d_in[6];
    const float* W1    = (const float*)d_in[7];
    const float* W2    = (const float*)d_in[8];
    const float* V0    = (const float*)d_in[9];
    const float* c0    = (const float*)d_in[10];
    const float* V1    = (const float*)d_in[11];
    const float* V2    = (const float*)d_in[12];
    const float* alpha = (const float*)d_in[13];
    float* out = (float*)d_out;

    convert_w<<<880, 256>>>(W0, W1, W2, V0, V1, V2);
    norm_kernel<<<NROWS / 8, 256>>>(x, nw0, nb0, nw1, nw2);

    // stage 1
    mma_kernel<128, 128, 0><<<dim3(512, 7, 1), 256>>>(b0, nullptr, nullptr, nullptr);
    mma_kernel< 64, 128, 1><<<dim3(512, 2, 3), 256>>>(nullptr, nullptr, nullptr, nullptr);
    mma_kernel< 64, 128, 2><<<dim3(512, 1, 5), 256>>>(nullptr, nullptr, nullptr, nullptr);
    // stage 2
    mma_kernel<512, 128, 3><<<dim3(512, 1, 1), 256>>>(c0, x, alpha, out);
    mma_kernel<256,  64, 4><<<dim3(512, 1, 3), 256>>>(nullptr, x, alpha, out);
    mma_kernel<128,  32, 5><<<dim3(512, 1, 5), 256>>>(nullptr, x, alpha, out);
}

// round 7
// speedup vs baseline: 1.9549x; 1.0787x over previous
#include <cuda_runtime.h>
#include <cuda_bf16.h>
#include <math.h>
#include <cstdint>

#define NROWS 65536
#define DIN   480
#define H0D   512
#define GDIM  384

// ================= scratch (device globals; no allocation) =================
__device__ __nv_bfloat16 gY0b[(size_t)NROWS * 128];       // y0 /sqrt(128)
__device__ __nv_bfloat16 gY1b[(size_t)3 * NROWS * 64];    // [m][row][64]
__device__ __nv_bfloat16 gY2b[(size_t)5 * NROWS * 64];    // [m][row][64] (k 32..63 zero)
__device__ __nv_bfloat16 gSb [(size_t)NROWS * 512];       // silu(h0)/sqrt(512)
__device__ float         gG  [(size_t)NROWS * GDIM];      // sigmoid gates (fp32)
__device__ __nv_bfloat16 gZ1b[(size_t)3 * NROWS * 256];   // z1/sqrt(256)
__device__ __nv_bfloat16 gZ2b[(size_t)5 * NROWS * 128];   // z2/sqrt(128)
// transposed bf16 weights  Wt[p][k]
__device__ __nv_bfloat16 gWt0[(size_t)896 * 128];
__device__ __nv_bfloat16 gWt1[(size_t)256 * 64];
__device__ __nv_bfloat16 gWt2[(size_t)128 * 64];          // k 32..63 zero
__device__ __nv_bfloat16 gVt0[(size_t)128 * 512];
__device__ __nv_bfloat16 gVt1[(size_t)64 * 256];
__device__ __nv_bfloat16 gVt2[(size_t)32 * 128];

// ================= helpers =================
__device__ __forceinline__ uint32_t smem_to_u32(const void* p) {
    uint32_t a;
    asm("{ .reg .u64 t; cvta.to.shared.u64 t, %1; cvt.u32.u64 %0, t; }" : "=r"(a) : "l"(p));
    return a;
}
#define SWZ(b) ((b) ^ (((b) >> 3) & 0x70))

__device__ __forceinline__ void cp16(uint32_t saddr, const void* g) {
    asm volatile("cp.async.cg.shared.global [%0], [%1], 16;" :: "r"(saddr), "l"(g));
}
__device__ __forceinline__ void cp_commit() {
    asm volatile("cp.async.commit_group;" ::: "memory");
}
__device__ __forceinline__ void cp_wait2() {
    asm volatile("cp.async.wait_group 2;" ::: "memory");
}

__device__ __forceinline__ void ldsm_x4(uint32_t* r, uint32_t addr) {
    asm volatile("ldmatrix.sync.aligned.m8n8.x4.shared.b16 {%0,%1,%2,%3}, [%4];"
        : "=r"(r[0]), "=r"(r[1]), "=r"(r[2]), "=r"(r[3]) : "r"(addr));
}
__device__ __forceinline__ void ldsm_x2(uint32_t* r, uint32_t addr) {
    asm volatile("ldmatrix.sync.aligned.m8n8.x2.shared.b16 {%0,%1}, [%2];"
        : "=r"(r[0]), "=r"(r[1]) : "r"(addr));
}
__device__ __forceinline__ void mma16816(float* d, const uint32_t* a, const uint32_t* b) {
    asm volatile(
        "mma.sync.aligned.m16n8k16.row.col.f32.bf16.bf16.f32 "
        "{%0,%1,%2,%3}, {%4,%5,%6,%7}, {%8,%9}, {%0,%1,%2,%3};"
        : "+f"(d[0]), "+f"(d[1]), "+f"(d[2]), "+f"(d[3])
        : "r"(a[0]), "r"(a[1]), "r"(a[2]), "r"(a[3]), "r"(b[0]), "r"(b[1]));
}
__device__ __forceinline__ float sigmf(float v) { return 1.0f / (1.0f + __expf(-v)); }

// ================= kernel 0: weight convert+transpose =================
__global__ void __launch_bounds__(256) convert_w(
    const float* __restrict__ W0, const float* __restrict__ W1, const float* __restrict__ W2,
    const float* __restrict__ V0, const float* __restrict__ V1, const float* __restrict__ V2)
{
    int i = blockIdx.x * 256 + threadIdx.x;
    if (i < 114688) {                       // Wt0[896][128] <- W0[128][896]
        int p = i / 128, k = i % 128;
        gWt0[i] = __float2bfloat16(W0[k * 896 + p]);
    } else if ((i -= 114688) < 16384) {     // Wt1[256][64] <- W1[64][256]
        int p = i / 64, k = i % 64;
        gWt1[i] = __float2bfloat16(W1[k * 256 + p]);
    } else if ((i -= 16384) < 8192) {       // Wt2[128][64] <- W2[32][128], pad
        int p = i / 64, k = i % 64;
        gWt2[i] = (k < 32) ? __float2bfloat16(W2[k * 128 + p]) : __float2bfloat16(0.f);
    } else if ((i -= 8192) < 65536) {       // Vt0[128][512] <- V0[512][128]
        int p = i / 512, k = i % 512;
        gVt0[i] = __float2bfloat16(V0[k * 128 + p]);
    } else if ((i -= 65536) < 16384) {      // Vt1[64][256] <- V1[256][64]
        int p = i / 256, k = i % 256;
        gVt1[i] = __float2bfloat16(V1[k * 64 + p]);
    } else if ((i -= 16384) < 4096) {       // Vt2[32][128] <- V2[128][32]
        int p = i / 128, k = i % 128;
        gVt2[i] = __float2bfloat16(V2[k * 32 + p]);
    }
}

// ================= kernel 1: norms (one warp per row) =================
__global__ void __launch_bounds__(256) norm_kernel(
    const float* __restrict__ x,  const float* __restrict__ nw0,
    const float* __restrict__ nb0, const float* __restrict__ nw1,
    const float* __restrict__ nw2)
{
    const int warp = threadIdx.x >> 5;
    const int lane = threadIdx.x & 31;
    const int row  = blockIdx.x * 8 + warp;
    const float* xr = x + (size_t)row * DIN;

    float4 v0 = ((const float4*)xr)[lane];
    float s = v0.x + v0.y + v0.z + v0.w;
    float q = v0.x*v0.x + v0.y*v0.y + v0.z*v0.z + v0.w*v0.w;
#pragma unroll
    for (int o = 16; o; o >>= 1) {
        s += __shfl_xor_sync(0xffffffffu, s, o);
        q += __shfl_xor_sync(0xffffffffu, q, o);
    }
    const float mu   = s * (1.0f / 128.0f);
    const float rstd = rsqrtf(q * (1.0f / 128.0f) - mu * mu + 1e-8f);

    float ss1 = 0.f, ss2 = 0.f;
    const float4* xr2 = (const float4*)(xr + 128);
#pragma unroll
    for (int j = lane; j < 88; j += 32) {
        float4 v = xr2[j];
        float d = v.x*v.x + v.y*v.y + v.z*v.z + v.w*v.w;
        if (j < 48) ss1 += d; else ss2 += d;
    }
#pragma unroll
    for (int o = 16; o; o >>= 1) {
        ss1 += __shfl_xor_sync(0xffffffffu, ss1, o);
        ss2 += __shfl_xor_sync(0xffffffffu, ss2, o);
    }
    const float inv = rsqrtf(0.5f * (ss1 * (1.f/192.f) + ss2 * (1.f/160.f)) + 1e-8f);

    const float invS0 = 0.08838834764831845f;
    float4 w = ((const float4*)nw0)[lane];
    float4 b = ((const float4*)nb0)[lane];
    __nv_bfloat16* y0 = gY0b + (size_t)row * 128 + lane * 4;
    y0[0] = __float2bfloat16(((v0.x - mu) * rstd * w.x + b.x) * invS0);
    y0[1] = __float2bfloat16(((v0.y - mu) * rstd * w.y + b.y) * invS0);
    y0[2] = __float2bfloat16(((v0.z - mu) * rstd * w.z + b.z) * invS0);
    y0[3] = __float2bfloat16(((v0.w - mu) * rstd * w.w + b.w) * invS0);

#pragma unroll
    for (int t = 0; t < 2; ++t) {
        int u = lane + t * 32;
        float c = inv * nw1[u] * 0.125f;
#pragma unroll
        for (int m = 0; m < 3; ++m)
            gY1b[((size_t)m * NROWS + row) * 64 + u] = __float2bfloat16(xr[128 + 3*u + m] * c);
    }
    {
        int u = lane;
        float c = inv * nw2[u] * 0.17677669529663689f;
#pragma unroll
        for (int m = 0; m < 5; ++m) {
            size_t base = ((size_t)m * NROWS + row) * 64;
            gY2b[base + u]      = __float2bfloat16(xr[320 + 5*u + m] * c);
            gY2b[base + u + 32] = __float2bfloat16(0.f);
        }
    }
}

// ================= HMMA GEMM, persistent CTAs + cp.async pipeline =================
// C[128 x NT] = A[128 x KdA] @ Wt[NT x KdA]^T  (bf16 in, fp32 acc)
// 8 warps: 2(m) x 4(n). K chunked by 64; 3-deep cp.async pipeline over
// flattened (row-tile, k-chunk) iterations; epilogue when chunk wraps.
template<int KdA, int NT, int EPI>
__global__ void __launch_bounds__(256, 2) mma_kernel(
    const float* __restrict__ bias, const float* __restrict__ X,
    const float* __restrict__ alphap, float* __restrict__ Out)
{
    constexpr int NCH   = KdA / 64;
    constexpr int WT_N  = NT / 4;
    constexpr int NI    = WT_N / 8;
    constexpr int MI    = 4;
    constexpr int SAB   = 128 * 128;       // A stage bytes (128 rows x 128B)
    constexpr int SBB   = NT * 128;        // B stage bytes
    constexpr int STAGE = SAB + SBB;
    constexpr int DEPTH = 3;
    constexpr int NTILES = NROWS / 128;    // 512

    extern __shared__ __align__(16) char dsm[];
    const uint32_t sbase = smem_to_u32(dsm);

    const int tid  = threadIdx.x;
    const int wid  = tid >> 5;
    const int lane = tid & 31;
    const int wm   = wid >> 2;
    const int wn   = wid & 3;
    const int pb   = blockIdx.y * NT;
    const int m    = blockIdx.z;
    const int t0   = blockIdx.x;
    const int tstr = gridDim.x;

    const __nv_bfloat16* gA =
        (EPI == 0) ? gY0b : (EPI == 1) ? gY1b : (EPI == 2) ? gY2b :
        (EPI == 3) ? gSb  : (EPI == 4) ? gZ1b : gZ2b;
    const __nv_bfloat16* gBw =
        (EPI == 0) ? gWt0 : (EPI == 1) ? gWt1 : (EPI == 2) ? gWt2 :
        (EPI == 3) ? gVt0 : (EPI == 4) ? gVt1 : gVt2;
    const __nv_bfloat16* Am = gA + (size_t)m * NROWS * KdA;

    const int my_tiles = (t0 < NTILES) ? ((NTILES - 1 - t0) / tstr + 1) : 0;
    const int my_iters = my_tiles * NCH;

    // ---- load issuer: iteration idx -> (tile, chunk) into stage idx%DEPTH
    auto issue_load = [&](int idx) {
        const int tile = t0 + (idx / NCH) * tstr;
        const int ch   = idx % NCH;
        const uint32_t st = sbase + (uint32_t)(idx % DEPTH) * STAGE;
        const __nv_bfloat16* Ab = Am + (size_t)(tile * 128) * KdA + ch * 64;
#pragma unroll
        for (int t = 0; t < 4; ++t) {              // 128 rows x 8 xfers = 1024
            int i2 = tid + t * 256;
            int r = i2 >> 3, v = i2 & 7;
            cp16(st + SWZ(r * 128 + v * 16), Ab + (size_t)r * KdA + v * 8);
        }
        const __nv_bfloat16* Bb = gBw + (size_t)pb * KdA + ch * 64;
#pragma unroll
        for (int t = 0; t < NT / 32; ++t) {        // NT rows x 8 xfers = NT*8
            int i2 = tid + t * 256;
            int r = i2 >> 3, v = i2 & 7;
            cp16(st + SAB + SWZ(r * 128 + v * 16), Bb + (size_t)r * KdA + v * 8);
        }
    };

    float acc[MI][NI][4];
#pragma unroll
    for (int i = 0; i < MI; ++i)
#pragma unroll
        for (int j = 0; j < NI; ++j)
#pragma unroll
            for (int r = 0; r < 4; ++r) acc[i][j][r] = 0.f;

    const int a_rowoff = (lane & 7) + ((lane >> 3) & 1) * 8;
    const int a_khalf  = lane >> 4;
    const int laneb    = lane & 15;
    const int b_rowoff = laneb & 7;
    const int b_khalf  = laneb >> 3;
    const float ta = (EPI >= 3) ? tanhf(alphap[0]) : 0.0f;

    // prologue
#pragma unroll
    for (int i = 0; i < DEPTH; ++i) {
        if (i < my_iters) issue_load(i);
        cp_commit();
    }

#pragma unroll 1
    for (int it = 0; it < my_iters; ++it) {
        cp_wait2();
        __syncthreads();

        const uint32_t st = sbase + (uint32_t)(it % DEPTH) * STAGE;
#pragma unroll
        for (int ks = 0; ks < 4; ++ks) {
            const int kbyte = ks * 32;
            uint32_t af[MI][4], bf[NI][2];
#pragma unroll
            for (int mi = 0; mi < MI; ++mi) {
                int r = wm * 64 + mi * 16 + a_rowoff;
                ldsm_x4(af[mi], st + SWZ(r * 128 + kbyte + a_khalf * 16));
            }
#pragma unroll
            for (int ni = 0; ni < NI; ++ni) {
                int r = wn * WT_N + ni * 8 + b_rowoff;
                ldsm_x2(bf[ni], st + SAB + SWZ(r * 128 + kbyte + b_khalf * 16));
            }
#pragma unroll
            for (int mi = 0; mi < MI; ++mi)
#pragma unroll
                for (int ni = 0; ni < NI; ++ni)
                    mma16816(acc[mi][ni], af[mi], bf[ni]);
        }

        if ((it % NCH) == NCH - 1) {
            // ---------------- epilogue for this row tile ----------------
            const int tile = t0 + (it / NCH) * tstr;
            const int rowBase = tile * 128;
#pragma unroll
            for (int mi = 0; mi < MI; ++mi) {
                const int row0 = rowBase + wm * 64 + mi * 16 + (lane >> 2);
#pragma unroll
                for (int ni = 0; ni < NI; ++ni) {
                    const int p0 = pb + wn * WT_N + ni * 8 + (lane & 3) * 2;
#pragma unroll
                    for (int r = 0; r < 4; ++r) {
                        const int row = row0 + (r >> 1) * 8;
                        const int p   = p0 + (r & 1);
                        const float v = acc[mi][ni][r];
                        if (EPI == 0) {
                            float h = v + bias[p];
                            if (p < H0D) {   // uniform per block (pb mult of 128)
                                gSb[(size_t)row * 512 + p] =
                                    __float2bfloat16(h * sigmf(h) * 0.04419417382415922f);
                            } else {
                                gG[(size_t)row * GDIM + p - H0D] = sigmf(h);
                            }
                        } else if (EPI == 1) {
                            float g = gG[(size_t)row * GDIM + p];
                            gZ1b[((size_t)m * NROWS + row) * 256 + p] =
                                __float2bfloat16(v * g * 0.0625f);
                        } else if (EPI == 2) {
                            float g = gG[(size_t)row * GDIM + 256 + p];
                            gZ2b[((size_t)m * NROWS + row) * 128 + p] =
                                __float2bfloat16(v * g * 0.08838834764831845f);
                        } else if (EPI == 3) {
                            int o = row * DIN + p;
                            Out[o] = X[o] + ta * (v + bias[p]);
                        } else if (EPI == 4) {
                            int o = row * DIN + 128 + 3 * p + m;
                            Out[o] = X[o] + ta * v;
                        } else {
                            int o = row * DIN + 320 + 5 * p + m;
                            Out[o] = X[o] + ta * v;
                        }
                        acc[mi][ni][r] = 0.f;
                    }
                }
            }
        }

        __syncthreads();                 // everyone done reading stage
        if (it + DEPTH < my_iters) issue_load(it + DEPTH);
        cp_commit();                     // keep group accounting uniform
    }
}

// ================= launch =================
extern "C" void kernel_launch(void* const* d_in, const int* in_sizes, int n_in,
                              void* d_out, int out_size) {
    const float* x     = (const float*)d_in[0];
    const float* nw0   = (const float*)d_in[1];
    const float* nb0   = (const float*)d_in[2];
    const float* nw1   = (const float*)d_in[3];
    const float* nw2   = (const float*)d_in[4];
    const float* W0    = (const float*)d_in[5];
    const float* b0    = (const float*)d_in[6];
    const float* W1    = (const float*)d_in[7];
    const float* W2    = (const float*)d_in[8];
    const float* V0    = (const float*)d_in[9];
    const float* c0    = (const float*)d_in[10];
    const float* V1    = (const float*)d_in[11];
    const float* V2    = (const float*)d_in[12];
    const float* alpha = (const float*)d_in[13];
    float* out = (float*)d_out;

    constexpr int SM128 = 3 * (128 * 128 + 128 * 128);  // 96 KB
    constexpr int SM64  = 3 * (128 * 128 + 64 * 128);   // 72 KB
    constexpr int SM32  = 3 * (128 * 128 + 32 * 128);   // 60 KB
    cudaFuncSetAttribute(mma_kernel<128, 128, 0>, cudaFuncAttributeMaxDynamicSharedMemorySize, SM128);
    cudaFuncSetAttribute(mma_kernel< 64, 128, 1>, cudaFuncAttributeMaxDynamicSharedMemorySize, SM128);
    cudaFuncSetAttribute(mma_kernel< 64, 128, 2>, cudaFuncAttributeMaxDynamicSharedMemorySize, SM128);
    cudaFuncSetAttribute(mma_kernel<512, 128, 3>, cudaFuncAttributeMaxDynamicSharedMemorySize, SM128);
    cudaFuncSetAttribute(mma_kernel<256,  64, 4>, cudaFuncAttributeMaxDynamicSharedMemorySize, SM64);
    cudaFuncSetAttribute(mma_kernel<128,  32, 5>, cudaFuncAttributeMaxDynamicSharedMemorySize, SM32);

    convert_w<<<880, 256>>>(W0, W1, W2, V0, V1, V2);
    norm_kernel<<<NROWS / 8, 256>>>(x, nw0, nb0, nw1, nw2);

    // stage 1
    mma_kernel<128, 128, 0><<<dim3( 84, 7, 1), 256, SM128>>>(b0, nullptr, nullptr, nullptr);
    mma_kernel< 64, 128, 1><<<dim3( 98, 2, 3), 256, SM128>>>(nullptr, nullptr, nullptr, nullptr);
    mma_kernel< 64, 128, 2><<<dim3(118, 1, 5), 256, SM128>>>(nullptr, nullptr, nullptr, nullptr);
    // stage 2
    mma_kernel<512, 128, 3><<<dim3(296, 1, 1), 256, SM128>>>(c0, x, alpha, out);
    mma_kernel<256,  64, 4><<<dim3(196, 1, 3), 256, SM64 >>>(nullptr, x, alpha, out);
    mma_kernel<128,  32, 5><<<dim3(118, 1, 5), 256, SM32 >>>(nullptr, x, alpha, out);
}

// round 9
// speedup vs baseline: 3.5136x; 1.7973x over previous
#include <cuda_runtime.h>
#include <cuda_bf16.h>
#include <math.h>
#include <cstdint>

#define NROWS 65536
#define DIN   480
#define H0D   512
#define GDIM  384

// ================= scratch (device globals; no allocation) =================
__device__ __nv_bfloat16 gY0b[(size_t)NROWS * 128];       // y0 /sqrt(128)
__device__ __nv_bfloat16 gY1b[(size_t)3 * NROWS * 64];    // [m][row][64]
__device__ __nv_bfloat16 gY2b[(size_t)5 * NROWS * 64];    // [m][row][64] (k 32..63 zero)
__device__ __nv_bfloat16 gSb [(size_t)NROWS * 512];       // silu(h0)/sqrt(512)
__device__ float         gG  [(size_t)NROWS * GDIM];      // sigmoid gates (fp32)
__device__ __nv_bfloat16 gZ1b[(size_t)3 * NROWS * 256];   // z1*g/sqrt(256)
__device__ __nv_bfloat16 gZ2b[(size_t)5 * NROWS * 128];   // z2*g/sqrt(128)
__device__ float         gO1 [(size_t)3 * NROWS * 64];    // o1 (scale already in z1)
__device__ float         gO2 [(size_t)5 * NROWS * 32];    // o2
// transposed bf16 weights  Wt[p][k]
__device__ __nv_bfloat16 gWt0[(size_t)896 * 128];
__device__ __nv_bfloat16 gWt1[(size_t)256 * 64];
__device__ __nv_bfloat16 gWt2[(size_t)128 * 64];          // k 32..63 zero
__device__ __nv_bfloat16 gVt0[(size_t)128 * 512];
__device__ __nv_bfloat16 gVt1[(size_t)64 * 256];
__device__ __nv_bfloat16 gVt2[(size_t)32 * 128];

// ================= helpers =================
__device__ __forceinline__ uint32_t smem_to_u32(const void* p) {
    uint32_t a;
    asm("{ .reg .u64 t; cvta.to.shared.u64 t, %1; cvt.u32.u64 %0, t; }" : "=r"(a) : "l"(p));
    return a;
}
#define SWZ(b) ((b) ^ (((b) >> 3) & 0x70))

__device__ __forceinline__ void cp16(uint32_t saddr, const void* g) {
    asm volatile("cp.async.cg.shared.global [%0], [%1], 16;" :: "r"(saddr), "l"(g));
}
__device__ __forceinline__ void cp_commit() {
    asm volatile("cp.async.commit_group;" ::: "memory");
}
__device__ __forceinline__ void cp_wait2() {
    asm volatile("cp.async.wait_group 2;" ::: "memory");
}
__device__ __forceinline__ void cp_wait1() {
    asm volatile("cp.async.wait_group 1;" ::: "memory");
}

__device__ __forceinline__ void ldsm_x4(uint32_t* r, uint32_t addr) {
    asm volatile("ldmatrix.sync.aligned.m8n8.x4.shared.b16 {%0,%1,%2,%3}, [%4];"
        : "=r"(r[0]), "=r"(r[1]), "=r"(r[2]), "=r"(r[3]) : "r"(addr));
}
__device__ __forceinline__ void ldsm_x2(uint32_t* r, uint32_t addr) {
    asm volatile("ldmatrix.sync.aligned.m8n8.x2.shared.b16 {%0,%1}, [%2];"
        : "=r"(r[0]), "=r"(r[1]) : "r"(addr));
}
__device__ __forceinline__ void mma16816(float* d, const uint32_t* a, const uint32_t* b) {
    asm volatile(
        "mma.sync.aligned.m16n8k16.row.col.f32.bf16.bf16.f32 "
        "{%0,%1,%2,%3}, {%4,%5,%6,%7}, {%8,%9}, {%0,%1,%2,%3};"
        : "+f"(d[0]), "+f"(d[1]), "+f"(d[2]), "+f"(d[3])
        : "r"(a[0]), "r"(a[1]), "r"(a[2]), "r"(a[3]), "r"(b[0]), "r"(b[1]));
}
__device__ __forceinline__ float sigmf(float v) { return 1.0f / (1.0f + __expf(-v)); }

// ================= kernel 0: weight convert+transpose =================
__global__ void __launch_bounds__(256) convert_w(
    const float* __restrict__ W0, const float* __restrict__ W1, const float* __restrict__ W2,
    const float* __restrict__ V0, const float* __restrict__ V1, const float* __restrict__ V2)
{
    int i = blockIdx.x * 256 + threadIdx.x;
    if (i < 114688) {                       // Wt0[896][128] <- W0[128][896]
        int p = i / 128, k = i % 128;
        gWt0[i] = __float2bfloat16(W0[k * 896 + p]);
    } else if ((i -= 114688) < 16384) {     // Wt1[256][64] <- W1[64][256]
        int p = i / 64, k = i % 64;
        gWt1[i] = __float2bfloat16(W1[k * 256 + p]);
    } else if ((i -= 16384) < 8192) {       // Wt2[128][64] <- W2[32][128], pad
        int p = i / 64, k = i % 64;
        gWt2[i] = (k < 32) ? __float2bfloat16(W2[k * 128 + p]) : __float2bfloat16(0.f);
    } else if ((i -= 8192) < 65536) {       // Vt0[128][512] <- V0[512][128]
        int p = i / 512, k = i % 512;
        gVt0[i] = __float2bfloat16(V0[k * 128 + p]);
    } else if ((i -= 65536) < 16384) {      // Vt1[64][256] <- V1[256][64]
        int p = i / 256, k = i % 256;
        gVt1[i] = __float2bfloat16(V1[k * 64 + p]);
    } else if ((i -= 16384) < 4096) {       // Vt2[32][128] <- V2[128][32]
        int p = i / 128, k = i % 128;
        gVt2[i] = __float2bfloat16(V2[k * 32 + p]);
    }
}

// ================= kernel 1: norms (one warp per row) =================
__global__ void __launch_bounds__(256) norm_kernel(
    const float* __restrict__ x,  const float* __restrict__ nw0,
    const float* __restrict__ nb0, const float* __restrict__ nw1,
    const float* __restrict__ nw2)
{
    const int warp = threadIdx.x >> 5;
    const int lane = threadIdx.x & 31;
    const int row  = blockIdx.x * 8 + warp;
    const float* xr = x + (size_t)row * DIN;

    float4 v0 = ((const float4*)xr)[lane];
    float s = v0.x + v0.y + v0.z + v0.w;
    float q = v0.x*v0.x + v0.y*v0.y + v0.z*v0.z + v0.w*v0.w;
#pragma unroll
    for (int o = 16; o; o >>= 1) {
        s += __shfl_xor_sync(0xffffffffu, s, o);
        q += __shfl_xor_sync(0xffffffffu, q, o);
    }
    const float mu   = s * (1.0f / 128.0f);
    const float rstd = rsqrtf(q * (1.0f / 128.0f) - mu * mu + 1e-8f);

    float ss1 = 0.f, ss2 = 0.f;
    const float4* xr2 = (const float4*)(xr + 128);
#pragma unroll
    for (int j = lane; j < 88; j += 32) {
        float4 v = xr2[j];
        float d = v.x*v.x + v.y*v.y + v.z*v.z + v.w*v.w;
        if (j < 48) ss1 += d; else ss2 += d;
    }
#pragma unroll
    for (int o = 16; o; o >>= 1) {
        ss1 += __shfl_xor_sync(0xffffffffu, ss1, o);
        ss2 += __shfl_xor_sync(0xffffffffu, ss2, o);
    }
    const float inv = rsqrtf(0.5f * (ss1 * (1.f/192.f) + ss2 * (1.f/160.f)) + 1e-8f);

    const float invS0 = 0.08838834764831845f;
    float4 w = ((const float4*)nw0)[lane];
    float4 b = ((const float4*)nb0)[lane];
    __nv_bfloat16* y0 = gY0b + (size_t)row * 128 + lane * 4;
    y0[0] = __float2bfloat16(((v0.x - mu) * rstd * w.x + b.x) * invS0);
    y0[1] = __float2bfloat16(((v0.y - mu) * rstd * w.y + b.y) * invS0);
    y0[2] = __float2bfloat16(((v0.z - mu) * rstd * w.z + b.z) * invS0);
    y0[3] = __float2bfloat16(((v0.w - mu) * rstd * w.w + b.w) * invS0);

#pragma unroll
    for (int t = 0; t < 2; ++t) {
        int u = lane + t * 32;
        float c = inv * nw1[u] * 0.125f;
#pragma unroll
        for (int m = 0; m < 3; ++m)
            gY1b[((size_t)m * NROWS + row) * 64 + u] = __float2bfloat16(xr[128 + 3*u + m] * c);
    }
    {
        int u = lane;
        float c = inv * nw2[u] * 0.17677669529663689f;
#pragma unroll
        for (int m = 0; m < 5; ++m) {
            size_t base = ((size_t)m * NROWS + row) * 64;
            gY2b[base + u]      = __float2bfloat16(xr[320 + 5*u + m] * c);
            gY2b[base + u + 32] = __float2bfloat16(0.f);
        }
    }
}

// ================= HMMA GEMM, persistent CTAs + cp.async pipeline =================
// Used for EPI 0 (h0), 3 (o0, with residual), 4/5 (o1/o2 raw store).
template<int KdA, int NT, int EPI>
__global__ void __launch_bounds__(256, 2) mma_kernel(
    const float* __restrict__ bias, const float* __restrict__ X,
    const float* __restrict__ alphap, float* __restrict__ Out)
{
    constexpr int NCH   = KdA / 64;
    constexpr int WT_N  = NT / 4;
    constexpr int NI    = WT_N / 8;
    constexpr int MI    = 4;
    constexpr int SAB   = 128 * 128;
    constexpr int SBB   = NT * 128;
    constexpr int STAGE = SAB + SBB;
    constexpr int DEPTH = 3;
    constexpr int NTILES = NROWS / 128;

    extern __shared__ __align__(16) char dsm[];
    const uint32_t sbase = smem_to_u32(dsm);

    const int tid  = threadIdx.x;
    const int wid  = tid >> 5;
    const int lane = tid & 31;
    const int wm   = wid >> 2;
    const int wn   = wid & 3;
    const int pb   = blockIdx.y * NT;
    const int m    = blockIdx.z;
    const int t0   = blockIdx.x;
    const int tstr = gridDim.x;

    const __nv_bfloat16* gA =
        (EPI == 0) ? gY0b : (EPI == 3) ? gSb : (EPI == 4) ? gZ1b : gZ2b;
    const __nv_bfloat16* gBw =
        (EPI == 0) ? gWt0 : (EPI == 3) ? gVt0 : (EPI == 4) ? gVt1 : gVt2;
    const __nv_bfloat16* Am = gA + (size_t)m * NROWS * KdA;

    const int my_tiles = (t0 < NTILES) ? ((NTILES - 1 - t0) / tstr + 1) : 0;
    const int my_iters = my_tiles * NCH;

    auto issue_load = [&](int idx) {
        const int tile = t0 + (idx / NCH) * tstr;
        const int ch   = idx % NCH;
        const uint32_t st = sbase + (uint32_t)(idx % DEPTH) * STAGE;
        const __nv_bfloat16* Ab = Am + (size_t)(tile * 128) * KdA + ch * 64;
#pragma unroll
        for (int t = 0; t < 4; ++t) {
            int i2 = tid + t * 256;
            int r = i2 >> 3, v = i2 & 7;
            cp16(st + SWZ(r * 128 + v * 16), Ab + (size_t)r * KdA + v * 8);
        }
        const __nv_bfloat16* Bb = gBw + (size_t)pb * KdA + ch * 64;
#pragma unroll
        for (int t = 0; t < NT / 32; ++t) {
            int i2 = tid + t * 256;
            int r = i2 >> 3, v = i2 & 7;
            cp16(st + SAB + SWZ(r * 128 + v * 16), Bb + (size_t)r * KdA + v * 8);
        }
    };

    float acc[MI][NI][4];
#pragma unroll
    for (int i = 0; i < MI; ++i)
#pragma unroll
        for (int j = 0; j < NI; ++j)
#pragma unroll
            for (int r = 0; r < 4; ++r) acc[i][j][r] = 0.f;

    const int a_rowoff = (lane & 7) + ((lane >> 3) & 1) * 8;
    const int a_khalf  = lane >> 4;
    const int laneb    = lane & 15;
    const int b_rowoff = laneb & 7;
    const int b_khalf  = laneb >> 3;
    const float ta = (EPI == 3) ? tanhf(alphap[0]) : 0.0f;

#pragma unroll
    for (int i = 0; i < DEPTH; ++i) {
        if (i < my_iters) issue_load(i);
        cp_commit();
    }

#pragma unroll 1
    for (int it = 0; it < my_iters; ++it) {
        cp_wait2();
        __syncthreads();

        const uint32_t st = sbase + (uint32_t)(it % DEPTH) * STAGE;
#pragma unroll
        for (int ks = 0; ks < 4; ++ks) {
            const int kbyte = ks * 32;
            uint32_t af[MI][4], bf[NI][2];
#pragma unroll
            for (int mi = 0; mi < MI; ++mi) {
                int r = wm * 64 + mi * 16 + a_rowoff;
                ldsm_x4(af[mi], st + SWZ(r * 128 + kbyte + a_khalf * 16));
            }
#pragma unroll
            for (int ni = 0; ni < NI; ++ni) {
                int r = wn * WT_N + ni * 8 + b_rowoff;
                ldsm_x2(bf[ni], st + SAB + SWZ(r * 128 + kbyte + b_khalf * 16));
            }
#pragma unroll
            for (int mi = 0; mi < MI; ++mi)
#pragma unroll
                for (int ni = 0; ni < NI; ++ni)
                    mma16816(acc[mi][ni], af[mi], bf[ni]);
        }

        if ((it % NCH) == NCH - 1) {
            const int tile = t0 + (it / NCH) * tstr;
            const int rowBase = tile * 128;
#pragma unroll
            for (int mi = 0; mi < MI; ++mi) {
#pragma unroll
                for (int ni = 0; ni < NI; ++ni) {
                    const int p0 = pb + wn * WT_N + ni * 8 + (lane & 3) * 2;
#pragma unroll
                    for (int rp = 0; rp < 2; ++rp) {
                        const int row = rowBase + wm * 64 + mi * 16 + (lane >> 2) + rp * 8;
                        float v0 = acc[mi][ni][rp * 2];
                        float v1 = acc[mi][ni][rp * 2 + 1];
                        if (EPI == 0) {
                            float h0 = v0 + bias[p0];
                            float h1 = v1 + bias[p0 + 1];
                            if (p0 < H0D) {   // uniform per block
                                __nv_bfloat162 pk;
                                pk.x = __float2bfloat16(h0 * sigmf(h0) * 0.04419417382415922f);
                                pk.y = __float2bfloat16(h1 * sigmf(h1) * 0.04419417382415922f);
                                *(__nv_bfloat162*)(gSb + (size_t)row * 512 + p0) = pk;
                            } else {
                                float2 pk = {sigmf(h0), sigmf(h1)};
                                *(float2*)(gG + (size_t)row * GDIM + p0 - H0D) = pk;
                            }
                        } else if (EPI == 3) {
                            size_t o = (size_t)row * DIN + p0;
                            float2 xv = *(const float2*)(X + o);
                            float2 pk = {xv.x + ta * (v0 + bias[p0]),
                                         xv.y + ta * (v1 + bias[p0 + 1])};
                            *(float2*)(Out + o) = pk;
                        } else if (EPI == 4) {
                            float2 pk = {v0, v1};
                            *(float2*)(gO1 + ((size_t)m * NROWS + row) * 64 + p0) = pk;
                        } else {
                            float2 pk = {v0, v1};
                            *(float2*)(gO2 + ((size_t)m * NROWS + row) * 32 + p0) = pk;
                        }
                        acc[mi][ni][rp * 2] = 0.f;
                        acc[mi][ni][rp * 2 + 1] = 0.f;
                    }
                }
            }
        }

        __syncthreads();
        if (it + DEPTH < my_iters) issue_load(it + DEPTH);
        cp_commit();
    }
}

// ================= gated GEMM for z1/z2 (Kd=64, NT=64) =================
// z = (Y[m] @ Wt^T) * g * scale ; gate tile streamed via cp.async.
// Double-buffered A (per iter) + G (per row-tile); B loaded once.
template<int M, int EPI>   // EPI: 1 -> z1, 2 -> z2
__global__ void __launch_bounds__(256, 2) gated_kernel(int dummy)
{
    constexpr int NT     = 64;
    constexpr int GPITCH = 68;                 // floats, pad for bank spread
    constexpr int OFF_B  = 0;                  // 64*128 = 8KB
    constexpr int OFF_A  = 8192;               // 2 x 16KB
    constexpr int OFF_G  = 8192 + 2 * 16384;   // 2 x 34816
    constexpr int GBUF   = 128 * GPITCH * 4;
    constexpr int NTILES = NROWS / 128;
    constexpr int ZW     = (EPI == 1) ? 256 : 128;
    constexpr int GOFSB  = (EPI == 1) ? 0 : 256;

    extern __shared__ __align__(16) char dsm[];
    const uint32_t sbase = smem_to_u32(dsm);

    const int tid  = threadIdx.x;
    const int wid  = tid >> 5;
    const int lane = tid & 31;
    const int wm   = wid >> 2;       // 0..1
    const int wn   = wid & 3;        // 0..3 -> 16 cols each
    const int pb   = blockIdx.y * NT;
    const int t0   = blockIdx.x;
    const int tstr = gridDim.x;

    const __nv_bfloat16* gA  = (EPI == 1) ? gY1b : gY2b;
    const __nv_bfloat16* gBw = (EPI == 1) ? gWt1 : gWt2;
    __nv_bfloat16* gZ        = (EPI == 1) ? gZ1b : gZ2b;
    const float SCALE = (EPI == 1) ? 0.0625f : 0.08838834764831845f;

    const int my_tiles = (t0 < NTILES) ? ((NTILES - 1 - t0) / tstr + 1) : 0;
    const int my_iters = my_tiles * M;

    auto issue_load = [&](int j) {
        const int tl  = j / M;
        const int mm  = j % M;
        const int tile = t0 + tl * tstr;
        // A tile for (tile, mm)
        const __nv_bfloat16* Ab = gA + ((size_t)mm * NROWS + tile * 128) * 64;
        const uint32_t ab = sbase + OFF_A + (uint32_t)(j & 1) * 16384;
#pragma unroll
        for (int t = 0; t < 4; ++t) {
            int i2 = tid + t * 256;
            int r = i2 >> 3, v = i2 & 7;
            cp16(ab + SWZ(r * 128 + v * 16), Ab + (size_t)r * 64 + v * 8);
        }
        // B once
        if (j == 0) {
#pragma unroll
            for (int t = 0; t < 2; ++t) {
                int i2 = tid + t * 256;
                int r = i2 >> 3, v = i2 & 7;
                cp16(sbase + OFF_B + SWZ(r * 128 + v * 16),
                     gBw + (size_t)(pb + r) * 64 + v * 8);
            }
        }
        // G: on j==0 load tile0's gate; on j%M==1 load next tile's gate
        if (j == 0 || mm == 1) {
            int gt = (j == 0) ? 0 : tl + 1;
            if (gt < my_tiles) {
                int gtile = t0 + gt * tstr;
                uint32_t gb = sbase + OFF_G + (uint32_t)(gt & 1) * GBUF;
                const float* Gsrc = gG + (size_t)(gtile * 128) * GDIM + GOFSB + pb;
#pragma unroll
                for (int t = 0; t < 8; ++t) {
                    int i2 = tid + t * 256;
                    int r = i2 >> 4, v = i2 & 15;
                    cp16(gb + (uint32_t)(r * GPITCH * 4 + v * 16),
                         Gsrc + (size_t)r * GDIM + v * 4);
                }
            }
        }
    };

    float acc[4][2][4];
#pragma unroll
    for (int i = 0; i < 4; ++i)
#pragma unroll
        for (int j = 0; j < 2; ++j)
#pragma unroll
            for (int r = 0; r < 4; ++r) acc[i][j][r] = 0.f;

    const int a_rowoff = (lane & 7) + ((lane >> 3) & 1) * 8;
    const int a_khalf  = lane >> 4;
    const int laneb    = lane & 15;
    const int b_rowoff = laneb & 7;
    const int b_khalf  = laneb >> 3;

    // prologue (DEPTH=2)
#pragma unroll
    for (int i = 0; i < 2; ++i) {
        if (i < my_iters) issue_load(i);
        cp_commit();
    }

#pragma unroll 1
    for (int j = 0; j < my_iters; ++j) {
        cp_wait1();
        __syncthreads();

        const uint32_t ab = sbase + OFF_A + (uint32_t)(j & 1) * 16384;
        const float* Gf = (const float*)(dsm + OFF_G + (size_t)((j / M) & 1) * GBUF);
#pragma unroll
        for (int ks = 0; ks < 4; ++ks) {
            const int kbyte = ks * 32;
            uint32_t af[4][4], bf[2][2];
#pragma unroll
            for (int mi = 0; mi < 4; ++mi) {
                int r = wm * 64 + mi * 16 + a_rowoff;
                ldsm_x4(af[mi], ab + SWZ(r * 128 + kbyte + a_khalf * 16));
            }
#pragma unroll
            for (int ni = 0; ni < 2; ++ni) {
                int r = wn * 16 + ni * 8 + b_rowoff;
                ldsm_x2(bf[ni], sbase + OFF_B + SWZ(r * 128 + kbyte + b_khalf * 16));
            }
#pragma unroll
            for (int mi = 0; mi < 4; ++mi)
#pragma unroll
                for (int ni = 0; ni < 2; ++ni)
                    mma16816(acc[mi][ni], af[mi], bf[ni]);
        }

        // ---------------- gated epilogue ----------------
        {
            const int tile = t0 + (j / M) * tstr;
            const int mm   = j % M;
            const int rowBase = tile * 128;
#pragma unroll
            for (int mi = 0; mi < 4; ++mi) {
#pragma unroll
                for (int ni = 0; ni < 2; ++ni) {
                    const int pl = wn * 16 + ni * 8 + (lane & 3) * 2;
#pragma unroll
                    for (int rp = 0; rp < 2; ++rp) {
                        const int lrow = wm * 64 + mi * 16 + (lane >> 2) + rp * 8;
                        float2 g = *(const float2*)(Gf + lrow * GPITCH + pl);
                        float z0 = acc[mi][ni][rp * 2]     * g.x * SCALE;
                        float z1 = acc[mi][ni][rp * 2 + 1] * g.y * SCALE;
                        __nv_bfloat162 pk;
                        pk.x = __float2bfloat16(z0);
                        pk.y = __float2bfloat16(z1);
                        *(__nv_bfloat162*)(gZ + ((size_t)mm * NROWS + rowBase + lrow) * ZW
                                           + pb + pl) = pk;
                        acc[mi][ni][rp * 2] = 0.f;
                        acc[mi][ni][rp * 2 + 1] = 0.f;
                    }
                }
            }
        }

        __syncthreads();
        if (j + 2 < my_iters) issue_load(j + 2);
        cp_commit();
    }
}

// ================= final combine: out[:,128:480] = x + ta*gather(o1,o2) ====
// NOTE: 1/sqrt(H) scales are already folded into gZ1b/gZ2b, so o1/o2 are final.
__global__ void __launch_bounds__(256) combine_kernel(
    const float* __restrict__ x, const float* __restrict__ alphap,
    float* __restrict__ out)
{
    const int warp = threadIdx.x >> 5;
    const int lane = threadIdx.x & 31;
    const int row  = blockIdx.x * 8 + warp;
    const float ta = tanhf(alphap[0]);
    const float* xr = x + (size_t)row * DIN;
    float* outr = out + (size_t)row * DIN;

#pragma unroll
    for (int t = 0; t < 6; ++t) {          // cols 128..319
        int c = 128 + lane + t * 32;
        int d = c - 128;
        float o = gO1[((size_t)(d % 3) * NROWS + row) * 64 + d / 3];
        outr[c] = xr[c] + ta * o;
    }
#pragma unroll
    for (int t = 0; t < 5; ++t) {          // cols 320..479
        int c = 320 + lane + t * 32;
        int d = c - 320;
        float o = gO2[((size_t)(d % 5) * NROWS + row) * 32 + d / 5];
        outr[c] = xr[c] + ta * o;
    }
}

// ================= launch =================
extern "C" void kernel_launch(void* const* d_in, const int* in_sizes, int n_in,
                              void* d_out, int out_size) {
    const float* x     = (const float*)d_in[0];
    const float* nw0   = (const float*)d_in[1];
    const float* nb0   = (const float*)d_in[2];
    const float* nw1   = (const float*)d_in[3];
    const float* nw2   = (const float*)d_in[4];
    const float* W0    = (const float*)d_in[5];
    const float* b0    = (const float*)d_in[6];
    const float* W1    = (const float*)d_in[7];
    const float* W2    = (const float*)d_in[8];
    const float* V0    = (const float*)d_in[9];
    const float* c0    = (const float*)d_in[10];
    const float* V1    = (const float*)d_in[11];
    const float* V2    = (const float*)d_in[12];
    const float* alpha = (const float*)d_in[13];
    float* out = (float*)d_out;

    constexpr int SM128 = 3 * (128 * 128 + 128 * 128);  // 96 KB
    constexpr int SM64  = 3 * (128 * 128 + 64 * 128);   // 72 KB
    constexpr int SM32  = 3 * (128 * 128 + 32 * 128);   // 60 KB
    constexpr int SMG   = 8192 + 2 * 16384 + 2 * (128 * 68 * 4);  // 110592
    cudaFuncSetAttribute(mma_kernel<128, 128, 0>, cudaFuncAttributeMaxDynamicSharedMemorySize, SM128);
    cudaFuncSetAttribute(mma_kernel<512, 128, 3>, cudaFuncAttributeMaxDynamicSharedMemorySize, SM128);
    cudaFuncSetAttribute(mma_kernel<256,  64, 4>, cudaFuncAttributeMaxDynamicSharedMemorySize, SM64);
    cudaFuncSetAttribute(mma_kernel<128,  32, 5>, cudaFuncAttributeMaxDynamicSharedMemorySize, SM32);
    cudaFuncSetAttribute(gated_kernel<3, 1>, cudaFuncAttributeMaxDynamicSharedMemorySize, SMG);
    cudaFuncSetAttribute(gated_kernel<5, 2>, cudaFuncAttributeMaxDynamicSharedMemorySize, SMG);

    convert_w<<<880, 256>>>(W0, W1, W2, V0, V1, V2);
    norm_kernel<<<NROWS / 8, 256>>>(x, nw0, nb0, nw1, nw2);

    // stage 1
    mma_kernel<128, 128, 0><<<dim3( 84, 7, 1), 256, SM128>>>(b0, nullptr, nullptr, nullptr);
    gated_kernel<3, 1><<<dim3( 74, 4, 1), 256, SMG>>>(0);   // z1 (H1=256 -> 4 pb)
    gated_kernel<5, 2><<<dim3(148, 2, 1), 256, SMG>>>(0);   // z2 (H2=128 -> 2 pb)
    // stage 2
    mma_kernel<512, 128, 3><<<dim3(296, 1, 1), 256, SM128>>>(c0, x, alpha, out);
    mma_kernel<256,  64, 4><<<dim3(196, 1, 3), 256, SM64 >>>(nullptr, nullptr, nullptr, nullptr);
    mma_kernel<128,  32, 5><<<dim3(118, 1, 5), 256, SM32 >>>(nullptr, nullptr, nullptr, nullptr);
    // residual gather for cols 128..479
    combine_kernel<<<NROWS / 8, 256>>>(x, alpha, out);
}

// round 10
// speedup vs baseline: 3.7404x; 1.0646x over previous
#include <cuda_runtime.h>
#include <cuda_bf16.h>
#include <math.h>
#include <cstdint>

#define NROWS 65536
#define DIN   480
#define H0D   512
#define GDIM  384

// ================= scratch (device globals; no allocation) =================
__device__ __nv_bfloat16 gY0b[(size_t)NROWS * 128];       // y0 /sqrt(128)
__device__ __nv_bfloat16 gY1b[(size_t)3 * NROWS * 64];    // [m][row][64]
__device__ __nv_bfloat16 gY2b[(size_t)5 * NROWS * 64];    // [m][row][64] (k 32..63 zero)
__device__ __nv_bfloat16 gSb [(size_t)NROWS * 512];       // silu(h0)/sqrt(512)
__device__ float         gG  [(size_t)NROWS * GDIM];      // sigmoid gates (fp32)
__device__ __nv_bfloat16 gZ1b[(size_t)3 * NROWS * 256];   // z1*g/sqrt(256)
__device__ __nv_bfloat16 gZ2b[(size_t)5 * NROWS * 128];   // z2*g/sqrt(128)
__device__ float         gO1 [(size_t)3 * NROWS * 64];    // o1 (scale already in z1)
__device__ float         gO2 [(size_t)5 * NROWS * 32];    // o2
// transposed bf16 weights  Wt[p][k]
__device__ __nv_bfloat16 gWt0[(size_t)896 * 128];
__device__ __nv_bfloat16 gWt1[(size_t)256 * 64];
__device__ __nv_bfloat16 gWt2[(size_t)128 * 64];          // k 32..63 zero
__device__ __nv_bfloat16 gVt0[(size_t)128 * 512];
__device__ __nv_bfloat16 gVt1[(size_t)64 * 256];
__device__ __nv_bfloat16 gVt2[(size_t)32 * 128];

// ================= helpers =================
__device__ __forceinline__ uint32_t smem_to_u32(const void* p) {
    uint32_t a;
    asm("{ .reg .u64 t; cvta.to.shared.u64 t, %1; cvt.u32.u64 %0, t; }" : "=r"(a) : "l"(p));
    return a;
}
#define SWZ(b) ((b) ^ (((b) >> 3) & 0x70))

__device__ __forceinline__ void cp16(uint32_t saddr, const void* g) {
    asm volatile("cp.async.cg.shared.global [%0], [%1], 16;" :: "r"(saddr), "l"(g));
}
__device__ __forceinline__ void cp_commit() {
    asm volatile("cp.async.commit_group;" ::: "memory");
}
__device__ __forceinline__ void cp_wait2() {
    asm volatile("cp.async.wait_group 2;" ::: "memory");
}
__device__ __forceinline__ void cp_wait1() {
    asm volatile("cp.async.wait_group 1;" ::: "memory");
}

__device__ __forceinline__ void ldsm_x4(uint32_t* r, uint32_t addr) {
    asm volatile("ldmatrix.sync.aligned.m8n8.x4.shared.b16 {%0,%1,%2,%3}, [%4];"
        : "=r"(r[0]), "=r"(r[1]), "=r"(r[2]), "=r"(r[3]) : "r"(addr));
}
__device__ __forceinline__ void ldsm_x2(uint32_t* r, uint32_t addr) {
    asm volatile("ldmatrix.sync.aligned.m8n8.x2.shared.b16 {%0,%1}, [%2];"
        : "=r"(r[0]), "=r"(r[1]) : "r"(addr));
}
__device__ __forceinline__ void mma16816(float* d, const uint32_t* a, const uint32_t* b) {
    asm volatile(
        "mma.sync.aligned.m16n8k16.row.col.f32.bf16.bf16.f32 "
        "{%0,%1,%2,%3}, {%4,%5,%6,%7}, {%8,%9}, {%0,%1,%2,%3};"
        : "+f"(d[0]), "+f"(d[1]), "+f"(d[2]), "+f"(d[3])
        : "r"(a[0]), "r"(a[1]), "r"(a[2]), "r"(a[3]), "r"(b[0]), "r"(b[1]));
}
__device__ __forceinline__ float sigmf(float v) { return 1.0f / (1.0f + __expf(-v)); }

// ================= kernel 0: weight convert+transpose =================
__global__ void __launch_bounds__(256) convert_w(
    const float* __restrict__ W0, const float* __restrict__ W1, const float* __restrict__ W2,
    const float* __restrict__ V0, const float* __restrict__ V1, const float* __restrict__ V2)
{
    int i = blockIdx.x * 256 + threadIdx.x;
    if (i < 114688) {                       // Wt0[896][128] <- W0[128][896]
        int p = i / 128, k = i % 128;
        gWt0[i] = __float2bfloat16(W0[k * 896 + p]);
    } else if ((i -= 114688) < 16384) {     // Wt1[256][64] <- W1[64][256]
        int p = i / 64, k = i % 64;
        gWt1[i] = __float2bfloat16(W1[k * 256 + p]);
    } else if ((i -= 16384) < 8192) {       // Wt2[128][64] <- W2[32][128], pad
        int p = i / 64, k = i % 64;
        gWt2[i] = (k < 32) ? __float2bfloat16(W2[k * 128 + p]) : __float2bfloat16(0.f);
    } else if ((i -= 8192) < 65536) {       // Vt0[128][512] <- V0[512][128]
        int p = i / 512, k = i % 512;
        gVt0[i] = __float2bfloat16(V0[k * 128 + p]);
    } else if ((i -= 65536) < 16384) {      // Vt1[64][256] <- V1[256][64]
        int p = i / 256, k = i % 256;
        gVt1[i] = __float2bfloat16(V1[k * 64 + p]);
    } else if ((i -= 16384) < 4096) {       // Vt2[32][128] <- V2[128][32]
        int p = i / 128, k = i % 128;
        gVt2[i] = __float2bfloat16(V2[k * 32 + p]);
    }
}

// ================= kernel 1: norms (one warp per row) =================
__global__ void __launch_bounds__(256) norm_kernel(
    const float* __restrict__ x,  const float* __restrict__ nw0,
    const float* __restrict__ nb0, const float* __restrict__ nw1,
    const float* __restrict__ nw2)
{
    const int warp = threadIdx.x >> 5;
    const int lane = threadIdx.x & 31;
    const int row  = blockIdx.x * 8 + warp;
    const float* xr = x + (size_t)row * DIN;

    float4 v0 = ((const float4*)xr)[lane];
    float s = v0.x + v0.y + v0.z + v0.w;
    float q = v0.x*v0.x + v0.y*v0.y + v0.z*v0.z + v0.w*v0.w;
#pragma unroll
    for (int o = 16; o; o >>= 1) {
        s += __shfl_xor_sync(0xffffffffu, s, o);
        q += __shfl_xor_sync(0xffffffffu, q, o);
    }
    const float mu   = s * (1.0f / 128.0f);
    const float rstd = rsqrtf(q * (1.0f / 128.0f) - mu * mu + 1e-8f);

    float ss1 = 0.f, ss2 = 0.f;
    const float4* xr2 = (const float4*)(xr + 128);
#pragma unroll
    for (int j = lane; j < 88; j += 32) {
        float4 v = xr2[j];
        float d = v.x*v.x + v.y*v.y + v.z*v.z + v.w*v.w;
        if (j < 48) ss1 += d; else ss2 += d;
    }
#pragma unroll
    for (int o = 16; o; o >>= 1) {
        ss1 += __shfl_xor_sync(0xffffffffu, ss1, o);
        ss2 += __shfl_xor_sync(0xffffffffu, ss2, o);
    }
    const float inv = rsqrtf(0.5f * (ss1 * (1.f/192.f) + ss2 * (1.f/160.f)) + 1e-8f);

    const float invS0 = 0.08838834764831845f;
    float4 w = ((const float4*)nw0)[lane];
    float4 b = ((const float4*)nb0)[lane];
    __nv_bfloat16* y0 = gY0b + (size_t)row * 128 + lane * 4;
    y0[0] = __float2bfloat16(((v0.x - mu) * rstd * w.x + b.x) * invS0);
    y0[1] = __float2bfloat16(((v0.y - mu) * rstd * w.y + b.y) * invS0);
    y0[2] = __float2bfloat16(((v0.z - mu) * rstd * w.z + b.z) * invS0);
    y0[3] = __float2bfloat16(((v0.w - mu) * rstd * w.w + b.w) * invS0);

#pragma unroll
    for (int t = 0; t < 2; ++t) {
        int u = lane + t * 32;
        float c = inv * nw1[u] * 0.125f;
#pragma unroll
        for (int m = 0; m < 3; ++m)
            gY1b[((size_t)m * NROWS + row) * 64 + u] = __float2bfloat16(xr[128 + 3*u + m] * c);
    }
    {
        int u = lane;
        float c = inv * nw2[u] * 0.17677669529663689f;
#pragma unroll
        for (int m = 0; m < 5; ++m) {
            size_t base = ((size_t)m * NROWS + row) * 64;
            gY2b[base + u]      = __float2bfloat16(xr[320 + 5*u + m] * c);
            gY2b[base + u + 32] = __float2bfloat16(0.f);
        }
    }
}

// ================= HMMA GEMM, persistent CTAs + cp.async pipeline =================
// Used for EPI 0 (h0), 3 (o0, with residual), 4/5 (o1/o2 raw store).
template<int KdA, int NT, int EPI>
__global__ void __launch_bounds__(256, 2) mma_kernel(
    const float* __restrict__ bias, const float* __restrict__ X,
    const float* __restrict__ alphap, float* __restrict__ Out)
{
    constexpr int NCH   = KdA / 64;
    constexpr int WT_N  = NT / 4;
    constexpr int NI    = WT_N / 8;
    constexpr int MI    = 4;
    constexpr int SAB   = 128 * 128;
    constexpr int SBB   = NT * 128;
    constexpr int STAGE = SAB + SBB;
    constexpr int DEPTH = 3;
    constexpr int NTILES = NROWS / 128;

    extern __shared__ __align__(16) char dsm[];
    const uint32_t sbase = smem_to_u32(dsm);

    const int tid  = threadIdx.x;
    const int wid  = tid >> 5;
    const int lane = tid & 31;
    const int wm   = wid >> 2;
    const int wn   = wid & 3;
    const int pb   = blockIdx.y * NT;
    const int m    = blockIdx.z;
    const int t0   = blockIdx.x;
    const int tstr = gridDim.x;

    const __nv_bfloat16* gA =
        (EPI == 0) ? gY0b : (EPI == 3) ? gSb : (EPI == 4) ? gZ1b : gZ2b;
    const __nv_bfloat16* gBw =
        (EPI == 0) ? gWt0 : (EPI == 3) ? gVt0 : (EPI == 4) ? gVt1 : gVt2;
    const __nv_bfloat16* Am = gA + (size_t)m * NROWS * KdA;

    const int my_tiles = (t0 < NTILES) ? ((NTILES - 1 - t0) / tstr + 1) : 0;
    const int my_iters = my_tiles * NCH;

    auto issue_load = [&](int idx) {
        const int tile = t0 + (idx / NCH) * tstr;
        const int ch   = idx % NCH;
        const uint32_t st = sbase + (uint32_t)(idx % DEPTH) * STAGE;
        const __nv_bfloat16* Ab = Am + (size_t)(tile * 128) * KdA + ch * 64;
#pragma unroll
        for (int t = 0; t < 4; ++t) {
            int i2 = tid + t * 256;
            int r = i2 >> 3, v = i2 & 7;
            cp16(st + SWZ(r * 128 + v * 16), Ab + (size_t)r * KdA + v * 8);
        }
        const __nv_bfloat16* Bb = gBw + (size_t)pb * KdA + ch * 64;
#pragma unroll
        for (int t = 0; t < NT / 32; ++t) {
            int i2 = tid + t * 256;
            int r = i2 >> 3, v = i2 & 7;
            cp16(st + SAB + SWZ(r * 128 + v * 16), Bb + (size_t)r * KdA + v * 8);
        }
    };

    float acc[MI][NI][4];
#pragma unroll
    for (int i = 0; i < MI; ++i)
#pragma unroll
        for (int j = 0; j < NI; ++j)
#pragma unroll
            for (int r = 0; r < 4; ++r) acc[i][j][r] = 0.f;

    const int a_rowoff = (lane & 7) + ((lane >> 3) & 1) * 8;
    const int a_khalf  = lane >> 4;
    const int laneb    = lane & 15;
    const int b_rowoff = laneb & 7;
    const int b_khalf  = laneb >> 3;
    const float ta = (EPI == 3) ? tanhf(alphap[0]) : 0.0f;

#pragma unroll
    for (int i = 0; i < DEPTH; ++i) {
        if (i < my_iters) issue_load(i);
        cp_commit();
    }

#pragma unroll 1
    for (int it = 0; it < my_iters; ++it) {
        cp_wait2();
        __syncthreads();

        const uint32_t st = sbase + (uint32_t)(it % DEPTH) * STAGE;
#pragma unroll
        for (int ks = 0; ks < 4; ++ks) {
            const int kbyte = ks * 32;
            uint32_t af[MI][4], bf[NI][2];
#pragma unroll
            for (int mi = 0; mi < MI; ++mi) {
                int r = wm * 64 + mi * 16 + a_rowoff;
                ldsm_x4(af[mi], st + SWZ(r * 128 + kbyte + a_khalf * 16));
            }
#pragma unroll
            for (int ni = 0; ni < NI; ++ni) {
                int r = wn * WT_N + ni * 8 + b_rowoff;
                ldsm_x2(bf[ni], st + SAB + SWZ(r * 128 + kbyte + b_khalf * 16));
            }
#pragma unroll
            for (int mi = 0; mi < MI; ++mi)
#pragma unroll
                for (int ni = 0; ni < NI; ++ni)
                    mma16816(acc[mi][ni], af[mi], bf[ni]);
        }

        if ((it % NCH) == NCH - 1) {
            const int tile = t0 + (it / NCH) * tstr;
            const int rowBase = tile * 128;
#pragma unroll
            for (int mi = 0; mi < MI; ++mi) {
#pragma unroll
                for (int ni = 0; ni < NI; ++ni) {
                    const int p0 = pb + wn * WT_N + ni * 8 + (lane & 3) * 2;
#pragma unroll
                    for (int rp = 0; rp < 2; ++rp) {
                        const int row = rowBase + wm * 64 + mi * 16 + (lane >> 2) + rp * 8;
                        float v0 = acc[mi][ni][rp * 2];
                        float v1 = acc[mi][ni][rp * 2 + 1];
                        if (EPI == 0) {
                            float h0 = v0 + bias[p0];
                            float h1 = v1 + bias[p0 + 1];
                            if (p0 < H0D) {   // uniform per block
                                __nv_bfloat162 pk;
                                pk.x = __float2bfloat16(h0 * sigmf(h0) * 0.04419417382415922f);
                                pk.y = __float2bfloat16(h1 * sigmf(h1) * 0.04419417382415922f);
                                *(__nv_bfloat162*)(gSb + (size_t)row * 512 + p0) = pk;
                            } else {
                                float2 pk = {sigmf(h0), sigmf(h1)};
                                *(float2*)(gG + (size_t)row * GDIM + p0 - H0D) = pk;
                            }
                        } else if (EPI == 3) {
                            size_t o = (size_t)row * DIN + p0;
                            float2 xv = *(const float2*)(X + o);
                            float2 pk = {xv.x + ta * (v0 + bias[p0]),
                                         xv.y + ta * (v1 + bias[p0 + 1])};
                            *(float2*)(Out + o) = pk;
                        } else if (EPI == 4) {
                            float2 pk = {v0, v1};
                            *(float2*)(gO1 + ((size_t)m * NROWS + row) * 64 + p0) = pk;
                        } else {
                            float2 pk = {v0, v1};
                            *(float2*)(gO2 + ((size_t)m * NROWS + row) * 32 + p0) = pk;
                        }
                        acc[mi][ni][rp * 2] = 0.f;
                        acc[mi][ni][rp * 2 + 1] = 0.f;
                    }
                }
            }
        }

        __syncthreads();
        if (it + DEPTH < my_iters) issue_load(it + DEPTH);
        cp_commit();
    }
}

// ================= gated GEMM for z1/z2 (Kd<=64, NT=64) =================
// z = (Y[m] @ Wt^T) * g * scale. Gate tile streamed via cp.async (fp32,
// double-buffered per row tile). After MMA, z is staged bf16 into the
// just-consumed A buffer (swizzled), then stored to global with coalesced
// 16B rows. KS = number of k16 MMA steps (2 for z2's real K=32).
template<int M, int EPI, int KS>   // EPI: 1 -> z1, 2 -> z2
__global__ void __launch_bounds__(256, 2) gated_kernel(int dummy)
{
    constexpr int NT     = 64;
    constexpr int GPITCH = 68;                 // floats, pad for bank spread
    constexpr int OFF_B  = 0;                  // 64*128 = 8KB
    constexpr int OFF_A  = 8192;               // 2 x 16KB
    constexpr int OFF_G  = 8192 + 2 * 16384;   // 2 x 34816
    constexpr int GBUF   = 128 * GPITCH * 4;
    constexpr int NTILES = NROWS / 128;
    constexpr int ZW     = (EPI == 1) ? 256 : 128;
    constexpr int GOFSB  = (EPI == 1) ? 0 : 256;

    extern __shared__ __align__(16) char dsm[];
    const uint32_t sbase = smem_to_u32(dsm);

    const int tid  = threadIdx.x;
    const int wid  = tid >> 5;
    const int lane = tid & 31;
    const int wm   = wid >> 2;       // 0..1
    const int wn   = wid & 3;        // 0..3 -> 16 cols each
    const int pb   = blockIdx.y * NT;
    const int t0   = blockIdx.x;
    const int tstr = gridDim.x;

    const __nv_bfloat16* gA  = (EPI == 1) ? gY1b : gY2b;
    const __nv_bfloat16* gBw = (EPI == 1) ? gWt1 : gWt2;
    __nv_bfloat16* gZ        = (EPI == 1) ? gZ1b : gZ2b;
    const float SCALE = (EPI == 1) ? 0.0625f : 0.08838834764831845f;

    const int my_tiles = (t0 < NTILES) ? ((NTILES - 1 - t0) / tstr + 1) : 0;
    const int my_iters = my_tiles * M;

    auto issue_load = [&](int j) {
        const int tl  = j / M;
        const int mm  = j % M;
        const int tile = t0 + tl * tstr;
        // A tile for (tile, mm): KS==4 -> 128B rows; KS==2 -> 64B rows (rest unused)
        const __nv_bfloat16* Ab = gA + ((size_t)mm * NROWS + tile * 128) * 64;
        const uint32_t ab = sbase + OFF_A + (uint32_t)(j & 1) * 16384;
        if (KS == 4) {
#pragma unroll
            for (int t = 0; t < 4; ++t) {
                int i2 = tid + t * 256;
                int r = i2 >> 3, v = i2 & 7;
                cp16(ab + SWZ(r * 128 + v * 16), Ab + (size_t)r * 64 + v * 8);
            }
        } else {
#pragma unroll
            for (int t = 0; t < 2; ++t) {
                int i2 = tid + t * 256;
                int r = i2 >> 2, v = i2 & 3;
                cp16(ab + SWZ(r * 128 + v * 16), Ab + (size_t)r * 64 + v * 8);
            }
        }
        // B once
        if (j == 0) {
            if (KS == 4) {
#pragma unroll
                for (int t = 0; t < 2; ++t) {
                    int i2 = tid + t * 256;
                    int r = i2 >> 3, v = i2 & 7;
                    cp16(sbase + OFF_B + SWZ(r * 128 + v * 16),
                         gBw + (size_t)(pb + r) * 64 + v * 8);
                }
            } else {
                int r = tid >> 2, v = tid & 3;   // 64 rows x 4 xfers
                cp16(sbase + OFF_B + SWZ(r * 128 + v * 16),
                     gBw + (size_t)(pb + r) * 64 + v * 8);
            }
        }
        // G: on j==0 load tile0's gate; on j%M==1 load next tile's gate
        if (j == 0 || mm == 1) {
            int gt = (j == 0) ? 0 : tl + 1;
            if (gt < my_tiles) {
                int gtile = t0 + gt * tstr;
                uint32_t gb = sbase + OFF_G + (uint32_t)(gt & 1) * GBUF;
                const float* Gsrc = gG + (size_t)(gtile * 128) * GDIM + GOFSB + pb;
#pragma unroll
                for (int t = 0; t < 8; ++t) {
                    int i2 = tid + t * 256;
                    int r = i2 >> 4, v = i2 & 15;
                    cp16(gb + (uint32_t)(r * GPITCH * 4 + v * 16),
                         Gsrc + (size_t)r * GDIM + v * 4);
                }
            }
        }
    };

    float acc[4][2][4];
#pragma unroll
    for (int i = 0; i < 4; ++i)
#pragma unroll
        for (int j = 0; j < 2; ++j)
#pragma unroll
            for (int r = 0; r < 4; ++r) acc[i][j][r] = 0.f;

    const int a_rowoff = (lane & 7) + ((lane >> 3) & 1) * 8;
    const int a_khalf  = lane >> 4;
    const int laneb    = lane & 15;
    const int b_rowoff = laneb & 7;
    const int b_khalf  = laneb >> 3;

    // prologue (DEPTH=2)
#pragma unroll
    for (int i = 0; i < 2; ++i) {
        if (i < my_iters) issue_load(i);
        cp_commit();
    }

#pragma unroll 1
    for (int j = 0; j < my_iters; ++j) {
        cp_wait1();
        __syncthreads();

        const uint32_t ab = sbase + OFF_A + (uint32_t)(j & 1) * 16384;
        const float* Gf = (const float*)(dsm + OFF_G + (size_t)((j / M) & 1) * GBUF);
#pragma unroll
        for (int ks = 0; ks < KS; ++ks) {
            const int kbyte = ks * 32;
            uint32_t af[4][4], bf[2][2];
#pragma unroll
            for (int mi = 0; mi < 4; ++mi) {
                int r = wm * 64 + mi * 16 + a_rowoff;
                ldsm_x4(af[mi], ab + SWZ(r * 128 + kbyte + a_khalf * 16));
            }
#pragma unroll
            for (int ni = 0; ni < 2; ++ni) {
                int r = wn * 16 + ni * 8 + b_rowoff;
                ldsm_x2(bf[ni], sbase + OFF_B + SWZ(r * 128 + kbyte + b_khalf * 16));
            }
#pragma unroll
            for (int mi = 0; mi < 4; ++mi)
#pragma unroll
                for (int ni = 0; ni < 2; ++ni)
                    mma16816(acc[mi][ni], af[mi], bf[ni]);
        }

        // ---- gate + stage z (bf16) into the consumed A buffer ----
        __syncthreads();                     // all warps done reading A stage
#pragma unroll
        for (int mi = 0; mi < 4; ++mi) {
#pragma unroll
            for (int ni = 0; ni < 2; ++ni) {
                const int pl = wn * 16 + ni * 8 + (lane & 3) * 2;   // bf16 col
#pragma unroll
                for (int rp = 0; rp < 2; ++rp) {
                    const int lrow = wm * 64 + mi * 16 + (lane >> 2) + rp * 8;
                    float2 g = *(const float2*)(Gf + lrow * GPITCH + pl);
                    __nv_bfloat162 pk;
                    pk.x = __float2bfloat16(acc[mi][ni][rp * 2]     * g.x * SCALE);
                    pk.y = __float2bfloat16(acc[mi][ni][rp * 2 + 1] * g.y * SCALE);
                    *(uint32_t*)(dsm + OFF_A + (size_t)(j & 1) * 16384
                                 + SWZ(lrow * 128 + pl * 2)) = *(uint32_t*)&pk;
                    acc[mi][ni][rp * 2] = 0.f;
                    acc[mi][ni][rp * 2 + 1] = 0.f;
                }
            }
        }
        __syncthreads();                     // z tile fully staged

        // ---- coalesced copy out: 128 rows x 128B ----
        {
            const int tile = t0 + (j / M) * tstr;
            const int mm   = j % M;
            const int rowBase = tile * 128;
            const int r0 = tid >> 3, v = tid & 7;
#pragma unroll
            for (int t = 0; t < 4; ++t) {
                int r = r0 + t * 32;
                uint4 d = *(const uint4*)(dsm + OFF_A + (size_t)(j & 1) * 16384
                                          + SWZ(r * 128 + v * 16));
                *(uint4*)(gZ + ((size_t)mm * NROWS + rowBase + r) * ZW + pb + v * 8) = d;
            }
        }

        __syncthreads();                     // copies done before stage reuse
        if (j + 2 < my_iters) issue_load(j + 2);
        cp_commit();
    }
}

// ================= final combine: out[:,128:480] = x + ta*gather(o1,o2) ====
// NOTE: 1/sqrt(H) scales are already folded into gZ1b/gZ2b, so o1/o2 are final.
__global__ void __launch_bounds__(256) combine_kernel(
    const float* __restrict__ x, const float* __restrict__ alphap,
    float* __restrict__ out)
{
    const int warp = threadIdx.x >> 5;
    const int lane = threadIdx.x & 31;
    const int row  = blockIdx.x * 8 + warp;
    const float ta = tanhf(alphap[0]);
    const float* xr = x + (size_t)row * DIN;
    float* outr = out + (size_t)row * DIN;

#pragma unroll
    for (int t = 0; t < 6; ++t) {          // cols 128..319
        int c = 128 + lane + t * 32;
        int d = c - 128;
        float o = gO1[((size_t)(d % 3) * NROWS + row) * 64 + d / 3];
        outr[c] = xr[c] + ta * o;
    }
#pragma unroll
    for (int t = 0; t < 5; ++t) {          // cols 320..479
        int c = 320 + lane + t * 32;
        int d = c - 320;
        float o = gO2[((size_t)(d % 5) * NROWS + row) * 32 + d / 5];
        outr[c] = xr[c] + ta * o;
    }
}

// ================= launch =================
extern "C" void kernel_launch(void* const* d_in, const int* in_sizes, int n_in,
                              void* d_out, int out_size) {
    const float* x     = (const float*)d_in[0];
    const float* nw0   = (const float*)d_in[1];
    const float* nb0   = (const float*)d_in[2];
    const float* nw1   = (const float*)d_in[3];
    const float* nw2   = (const float*)d_in[4];
    const float* W0    = (const float*)d_in[5];
    const float* b0    = (const float*)d_in[6];
    const float* W1    = (const float*)d_in[7];
    const float* W2    = (const float*)d_in[8];
    const float* V0    = (const float*)d_in[9];
    const float* c0    = (const float*)d_in[10];
    const float* V1    = (const float*)d_in[11];
    const float* V2    = (const float*)d_in[12];
    const float* alpha = (const float*)d_in[13];
    float* out = (float*)d_out;

    constexpr int SM128 = 3 * (128 * 128 + 128 * 128);  // 96 KB
    constexpr int SM64  = 3 * (128 * 128 + 64 * 128);   // 72 KB
    constexpr int SM32  = 3 * (128 * 128 + 32 * 128);   // 60 KB
    constexpr int SMG   = 8192 + 2 * 16384 + 2 * (128 * 68 * 4);  // 110592
    cudaFuncSetAttribute(mma_kernel<128, 128, 0>, cudaFuncAttributeMaxDynamicSharedMemorySize, SM128);
    cudaFuncSetAttribute(mma_kernel<512, 128, 3>, cudaFuncAttributeMaxDynamicSharedMemorySize, SM128);
    cudaFuncSetAttribute(mma_kernel<256,  64, 4>, cudaFuncAttributeMaxDynamicSharedMemorySize, SM64);
    cudaFuncSetAttribute(mma_kernel<128,  32, 5>, cudaFuncAttributeMaxDynamicSharedMemorySize, SM32);
    cudaFuncSetAttribute(gated_kernel<3, 1, 4>, cudaFuncAttributeMaxDynamicSharedMemorySize, SMG);
    cudaFuncSetAttribute(gated_kernel<5, 2, 2>, cudaFuncAttributeMaxDynamicSharedMemorySize, SMG);

    convert_w<<<880, 256>>>(W0, W1, W2, V0, V1, V2);
    norm_kernel<<<NROWS / 8, 256>>>(x, nw0, nb0, nw1, nw2);

    // stage 1
    mma_kernel<128, 128, 0><<<dim3( 84, 7, 1), 256, SM128>>>(b0, nullptr, nullptr, nullptr);
    gated_kernel<3, 1, 4><<<dim3( 74, 4, 1), 256, SMG>>>(0);   // z1 (H1=256 -> 4 pb)
    gated_kernel<5, 2, 2><<<dim3(148, 2, 1), 256, SMG>>>(0);   // z2 (H2=128 -> 2 pb)
    // stage 2
    mma_kernel<512, 128, 3><<<dim3(296, 1, 1), 256, SM128>>>(c0, x, alpha, out);
    mma_kernel<256,  64, 4><<<dim3(196, 1, 3), 256, SM64 >>>(nullptr, nullptr, nullptr, nullptr);
    mma_kernel<128,  32, 5><<<dim3(118, 1, 5), 256, SM32 >>>(nullptr, nullptr, nullptr, nullptr);
    // residual gather for cols 128..479
    combine_kernel<<<NROWS / 8, 256>>>(x, alpha, out);
}

// round 11
// speedup vs baseline: 3.7512x; 1.0029x over previous
#include <cuda_runtime.h>
#include <cuda_bf16.h>
#include <math.h>
#include <cstdint>

#define NROWS 65536
#define DIN   480
#define H0D   512
#define GDIM  384

// ================= scratch (device globals; no allocation) =================
__device__ __nv_bfloat16 gY0b[(size_t)NROWS * 128];       // y0 /sqrt(128)
__device__ __nv_bfloat16 gY1b[(size_t)3 * NROWS * 64];    // [m][row][64]
__device__ __nv_bfloat16 gY2b[(size_t)5 * NROWS * 64];    // [m][row][64] (only k<32 used)
__device__ __nv_bfloat16 gSb [(size_t)NROWS * 512];       // silu(h0)/sqrt(512)
__device__ float         gG  [(size_t)NROWS * GDIM];      // sigmoid gates (fp32)
__device__ float         gO1 [(size_t)3 * NROWS * 64];    // o1 (scales folded)
__device__ float         gO2 [(size_t)5 * NROWS * 32];    // o2
// transposed bf16 weights  Wt[p][k]
__device__ __nv_bfloat16 gWt0[(size_t)896 * 128];
__device__ __nv_bfloat16 gWt1[(size_t)256 * 64];
__device__ __nv_bfloat16 gWt2[(size_t)128 * 64];          // k 32..63 zero (unused)
__device__ __nv_bfloat16 gVt0[(size_t)128 * 512];
__device__ __nv_bfloat16 gVt1[(size_t)64 * 256];
__device__ __nv_bfloat16 gVt2[(size_t)32 * 128];

// ================= helpers =================
__device__ __forceinline__ uint32_t smem_to_u32(const void* p) {
    uint32_t a;
    asm("{ .reg .u64 t; cvta.to.shared.u64 t, %1; cvt.u32.u64 %0, t; }" : "=r"(a) : "l"(p));
    return a;
}
#define SWZ(b) ((b) ^ (((b) >> 3) & 0x70))

__device__ __forceinline__ void cp16(uint32_t saddr, const void* g) {
    asm volatile("cp.async.cg.shared.global [%0], [%1], 16;" :: "r"(saddr), "l"(g));
}
__device__ __forceinline__ void cp_commit() {
    asm volatile("cp.async.commit_group;" ::: "memory");
}
__device__ __forceinline__ void cp_wait2() {
    asm volatile("cp.async.wait_group 2;" ::: "memory");
}
__device__ __forceinline__ void cp_wait1() {
    asm volatile("cp.async.wait_group 1;" ::: "memory");
}

__device__ __forceinline__ void ldsm_x4(uint32_t* r, uint32_t addr) {
    asm volatile("ldmatrix.sync.aligned.m8n8.x4.shared.b16 {%0,%1,%2,%3}, [%4];"
        : "=r"(r[0]), "=r"(r[1]), "=r"(r[2]), "=r"(r[3]) : "r"(addr));
}
__device__ __forceinline__ void ldsm_x2(uint32_t* r, uint32_t addr) {
    asm volatile("ldmatrix.sync.aligned.m8n8.x2.shared.b16 {%0,%1}, [%2];"
        : "=r"(r[0]), "=r"(r[1]) : "r"(addr));
}
__device__ __forceinline__ void mma16816(float* d, const uint32_t* a, const uint32_t* b) {
    asm volatile(
        "mma.sync.aligned.m16n8k16.row.col.f32.bf16.bf16.f32 "
        "{%0,%1,%2,%3}, {%4,%5,%6,%7}, {%8,%9}, {%0,%1,%2,%3};"
        : "+f"(d[0]), "+f"(d[1]), "+f"(d[2]), "+f"(d[3])
        : "r"(a[0]), "r"(a[1]), "r"(a[2]), "r"(a[3]), "r"(b[0]), "r"(b[1]));
}
__device__ __forceinline__ float sigmf(float v) { return 1.0f / (1.0f + __expf(-v)); }

// ================= kernel 0: weight convert+transpose =================
__global__ void __launch_bounds__(256) convert_w(
    const float* __restrict__ W0, const float* __restrict__ W1, const float* __restrict__ W2,
    const float* __restrict__ V0, const float* __restrict__ V1, const float* __restrict__ V2)
{
    int i = blockIdx.x * 256 + threadIdx.x;
    if (i < 114688) {                       // Wt0[896][128] <- W0[128][896]
        int p = i / 128, k = i % 128;
        gWt0[i] = __float2bfloat16(W0[k * 896 + p]);
    } else if ((i -= 114688) < 16384) {     // Wt1[256][64] <- W1[64][256]
        int p = i / 64, k = i % 64;
        gWt1[i] = __float2bfloat16(W1[k * 256 + p]);
    } else if ((i -= 16384) < 8192) {       // Wt2[128][64] <- W2[32][128], pad
        int p = i / 64, k = i % 64;
        gWt2[i] = (k < 32) ? __float2bfloat16(W2[k * 128 + p]) : __float2bfloat16(0.f);
    } else if ((i -= 8192) < 65536) {       // Vt0[128][512] <- V0[512][128]
        int p = i / 512, k = i % 512;
        gVt0[i] = __float2bfloat16(V0[k * 128 + p]);
    } else if ((i -= 65536) < 16384) {      // Vt1[64][256] <- V1[256][64]
        int p = i / 256, k = i % 256;
        gVt1[i] = __float2bfloat16(V1[k * 64 + p]);
    } else if ((i -= 16384) < 4096) {       // Vt2[32][128] <- V2[128][32]
        int p = i / 128, k = i % 128;
        gVt2[i] = __float2bfloat16(V2[k * 32 + p]);
    }
}

// ================= kernel 1: norms (one warp per row) =================
__global__ void __launch_bounds__(256) norm_kernel(
    const float* __restrict__ x,  const float* __restrict__ nw0,
    const float* __restrict__ nb0, const float* __restrict__ nw1,
    const float* __restrict__ nw2)
{
    const int warp = threadIdx.x >> 5;
    const int lane = threadIdx.x & 31;
    const int row  = blockIdx.x * 8 + warp;
    const float* xr = x + (size_t)row * DIN;

    float4 v0 = ((const float4*)xr)[lane];
    float s = v0.x + v0.y + v0.z + v0.w;
    float q = v0.x*v0.x + v0.y*v0.y + v0.z*v0.z + v0.w*v0.w;
#pragma unroll
    for (int o = 16; o; o >>= 1) {
        s += __shfl_xor_sync(0xffffffffu, s, o);
        q += __shfl_xor_sync(0xffffffffu, q, o);
    }
    const float mu   = s * (1.0f / 128.0f);
    const float rstd = rsqrtf(q * (1.0f / 128.0f) - mu * mu + 1e-8f);

    float ss1 = 0.f, ss2 = 0.f;
    const float4* xr2 = (const float4*)(xr + 128);
#pragma unroll
    for (int j = lane; j < 88; j += 32) {
        float4 v = xr2[j];
        float d = v.x*v.x + v.y*v.y + v.z*v.z + v.w*v.w;
        if (j < 48) ss1 += d; else ss2 += d;
    }
#pragma unroll
    for (int o = 16; o; o >>= 1) {
        ss1 += __shfl_xor_sync(0xffffffffu, ss1, o);
        ss2 += __shfl_xor_sync(0xffffffffu, ss2, o);
    }
    const float inv = rsqrtf(0.5f * (ss1 * (1.f/192.f) + ss2 * (1.f/160.f)) + 1e-8f);

    const float invS0 = 0.08838834764831845f;
    float4 w = ((const float4*)nw0)[lane];
    float4 b = ((const float4*)nb0)[lane];
    __nv_bfloat16* y0 = gY0b + (size_t)row * 128 + lane * 4;
    y0[0] = __float2bfloat16(((v0.x - mu) * rstd * w.x + b.x) * invS0);
    y0[1] = __float2bfloat16(((v0.y - mu) * rstd * w.y + b.y) * invS0);
    y0[2] = __float2bfloat16(((v0.z - mu) * rstd * w.z + b.z) * invS0);
    y0[3] = __float2bfloat16(((v0.w - mu) * rstd * w.w + b.w) * invS0);

#pragma unroll
    for (int t = 0; t < 2; ++t) {
        int u = lane + t * 32;
        float c = inv * nw1[u] * 0.125f;
#pragma unroll
        for (int m = 0; m < 3; ++m)
            gY1b[((size_t)m * NROWS + row) * 64 + u] = __float2bfloat16(xr[128 + 3*u + m] * c);
    }
    {
        int u = lane;
        float c = inv * nw2[u] * 0.17677669529663689f;
#pragma unroll
        for (int m = 0; m < 5; ++m)
            gY2b[((size_t)m * NROWS + row) * 64 + u] =
                __float2bfloat16(xr[320 + 5*u + m] * c);
    }
}

// ================= HMMA GEMM, persistent CTAs + cp.async pipeline =================
// EPI 0: h0 -> silu/gate ; EPI 3: o0 with residual.
template<int KdA, int NT, int EPI>
__global__ void __launch_bounds__(256, 2) mma_kernel(
    const float* __restrict__ bias, const float* __restrict__ X,
    const float* __restrict__ alphap, float* __restrict__ Out)
{
    constexpr int NCH   = KdA / 64;
    constexpr int WT_N  = NT / 4;
    constexpr int NI    = WT_N / 8;
    constexpr int MI    = 4;
    constexpr int SAB   = 128 * 128;
    constexpr int SBB   = NT * 128;
    constexpr int STAGE = SAB + SBB;
    constexpr int DEPTH = 3;
    constexpr int NTILES = NROWS / 128;

    extern __shared__ __align__(16) char dsm[];
    const uint32_t sbase = smem_to_u32(dsm);

    const int tid  = threadIdx.x;
    const int wid  = tid >> 5;
    const int lane = tid & 31;
    const int wm   = wid >> 2;
    const int wn   = wid & 3;
    const int pb   = blockIdx.y * NT;
    const int t0   = blockIdx.x;
    const int tstr = gridDim.x;

    const __nv_bfloat16* gA  = (EPI == 0) ? gY0b : gSb;
    const __nv_bfloat16* gBw = (EPI == 0) ? gWt0 : gVt0;

    const int my_tiles = (t0 < NTILES) ? ((NTILES - 1 - t0) / tstr + 1) : 0;
    const int my_iters = my_tiles * NCH;

    auto issue_load = [&](int idx) {
        const int tile = t0 + (idx / NCH) * tstr;
        const int ch   = idx % NCH;
        const uint32_t st = sbase + (uint32_t)(idx % DEPTH) * STAGE;
        const __nv_bfloat16* Ab = gA + (size_t)(tile * 128) * KdA + ch * 64;
#pragma unroll
        for (int t = 0; t < 4; ++t) {
            int i2 = tid + t * 256;
            int r = i2 >> 3, v = i2 & 7;
            cp16(st + SWZ(r * 128 + v * 16), Ab + (size_t)r * KdA + v * 8);
        }
        const __nv_bfloat16* Bb = gBw + (size_t)pb * KdA + ch * 64;
#pragma unroll
        for (int t = 0; t < NT / 32; ++t) {
            int i2 = tid + t * 256;
            int r = i2 >> 3, v = i2 & 7;
            cp16(st + SAB + SWZ(r * 128 + v * 16), Bb + (size_t)r * KdA + v * 8);
        }
    };

    float acc[MI][NI][4];
#pragma unroll
    for (int i = 0; i < MI; ++i)
#pragma unroll
        for (int j = 0; j < NI; ++j)
#pragma unroll
            for (int r = 0; r < 4; ++r) acc[i][j][r] = 0.f;

    const int a_rowoff = (lane & 7) + ((lane >> 3) & 1) * 8;
    const int a_khalf  = lane >> 4;
    const int laneb    = lane & 15;
    const int b_rowoff = laneb & 7;
    const int b_khalf  = laneb >> 3;
    const float ta = (EPI == 3) ? tanhf(alphap[0]) : 0.0f;

#pragma unroll
    for (int i = 0; i < DEPTH; ++i) {
        if (i < my_iters) issue_load(i);
        cp_commit();
    }

#pragma unroll 1
    for (int it = 0; it < my_iters; ++it) {
        cp_wait2();
        __syncthreads();

        const uint32_t st = sbase + (uint32_t)(it % DEPTH) * STAGE;
#pragma unroll
        for (int ks = 0; ks < 4; ++ks) {
            const int kbyte = ks * 32;
            uint32_t af[MI][4], bf[NI][2];
#pragma unroll
            for (int mi = 0; mi < MI; ++mi) {
                int r = wm * 64 + mi * 16 + a_rowoff;
                ldsm_x4(af[mi], st + SWZ(r * 128 + kbyte + a_khalf * 16));
            }
#pragma unroll
            for (int ni = 0; ni < NI; ++ni) {
                int r = wn * WT_N + ni * 8 + b_rowoff;
                ldsm_x2(bf[ni], st + SAB + SWZ(r * 128 + kbyte + b_khalf * 16));
            }
#pragma unroll
            for (int mi = 0; mi < MI; ++mi)
#pragma unroll
                for (int ni = 0; ni < NI; ++ni)
                    mma16816(acc[mi][ni], af[mi], bf[ni]);
        }

        if ((it % NCH) == NCH - 1) {
            const int tile = t0 + (it / NCH) * tstr;
            const int rowBase = tile * 128;
#pragma unroll
            for (int mi = 0; mi < MI; ++mi) {
#pragma unroll
                for (int ni = 0; ni < NI; ++ni) {
                    const int p0 = pb + wn * WT_N + ni * 8 + (lane & 3) * 2;
#pragma unroll
                    for (int rp = 0; rp < 2; ++rp) {
                        const int row = rowBase + wm * 64 + mi * 16 + (lane >> 2) + rp * 8;
                        float v0 = acc[mi][ni][rp * 2];
                        float v1 = acc[mi][ni][rp * 2 + 1];
                        if (EPI == 0) {
                            float h0 = v0 + bias[p0];
                            float h1 = v1 + bias[p0 + 1];
                            if (p0 < H0D) {   // uniform per block
                                __nv_bfloat162 pk;
                                pk.x = __float2bfloat16(h0 * sigmf(h0) * 0.04419417382415922f);
                                pk.y = __float2bfloat16(h1 * sigmf(h1) * 0.04419417382415922f);
                                *(__nv_bfloat162*)(gSb + (size_t)row * 512 + p0) = pk;
                            } else {
                                float2 pk = {sigmf(h0), sigmf(h1)};
                                *(float2*)(gG + (size_t)row * GDIM + p0 - H0D) = pk;
                            }
                        } else {
                            size_t o = (size_t)row * DIN + p0;
                            float2 xv = *(const float2*)(X + o);
                            float2 pk = {xv.x + ta * (v0 + bias[p0]),
                                         xv.y + ta * (v1 + bias[p0 + 1])};
                            *(float2*)(Out + o) = pk;
                        }
                        acc[mi][ni][rp * 2] = 0.f;
                        acc[mi][ni][rp * 2 + 1] = 0.f;
                    }
                }
            }
        }

        __syncthreads();
        if (it + DEPTH < my_iters) issue_load(it + DEPTH);
        cp_commit();
    }
}

// ================= fused z + down-projection per spectral branch =================
// For each (row tile, m): loop H in 64-col slabs s:
//   z_s = Y[m] @ Wt-slab-s ; stage bf16(z_s * g * scale) in smem ;
//   o  += z_s @ Vt-chunk-s   (k-chunk order s=0..NSLAB-1, identical to old path)
// o written directly to gO1/gO2 (no z round trip through global).
template<int M, int BR>   // BR=1: H=256,K=64 ; BR=2: H=128,K=32
__global__ void __launch_bounds__(256, 2) zo_kernel()
{
    constexpr int NSLAB  = (BR == 1) ? 4 : 2;       // H / 64
    constexpr int KSY    = (BR == 1) ? 4 : 2;       // k16 steps of the z GEMM
    constexpr int OW     = (BR == 1) ? 64 : 32;     // o columns
    constexpr int ONI    = OW / 32;                 // 2 / 1
    constexpr int GOFSB  = (BR == 1) ? 0 : 256;
    constexpr int WROWS  = (BR == 1) ? 256 : 128;
    constexpr int VROWS  = OW;
    constexpr int VCB    = VROWS * 128;             // bytes per Vt chunk
    constexpr int OFF_W  = 0;
    constexpr int OFF_V  = OFF_W + WROWS * 128;
    constexpr int OFF_Y  = OFF_V + NSLAB * VCB;
    constexpr int YB     = 128 * 128;
    constexpr int OFF_Z  = OFF_Y + 2 * YB;
    constexpr int NTILES = NROWS / 128;

    extern __shared__ __align__(16) char dsm[];
    const uint32_t sbase = smem_to_u32(dsm);

    const int tid  = threadIdx.x;
    const int wid  = tid >> 5;
    const int lane = tid & 31;
    const int wm   = wid >> 2;
    const int wn   = wid & 3;
    const int t0   = blockIdx.x;
    const int tstr = gridDim.x;

    const __nv_bfloat16* gA  = (BR == 1) ? gY1b : gY2b;
    const __nv_bfloat16* gWt = (BR == 1) ? gWt1 : gWt2;
    const __nv_bfloat16* gVt = (BR == 1) ? gVt1 : gVt2;
    float* gO = (BR == 1) ? gO1 : gO2;
    const float SCALE = (BR == 1) ? 0.0625f : 0.08838834764831845f;

    const int my_tiles = (t0 < NTILES) ? ((NTILES - 1 - t0) / tstr + 1) : 0;
    const int my_iters = my_tiles * M;

    auto issue_y = [&](int j) {
        const int tile = t0 + (j / M) * tstr;
        const int mm   = j % M;
        const __nv_bfloat16* Ab = gA + ((size_t)mm * NROWS + tile * 128) * 64;
        const uint32_t yb = sbase + OFF_Y + (uint32_t)(j & 1) * YB;
        if (KSY == 4) {
#pragma unroll
            for (int t = 0; t < 4; ++t) {
                int i2 = tid + t * 256;
                int r = i2 >> 3, v = i2 & 7;
                cp16(yb + SWZ(r * 128 + v * 16), Ab + (size_t)r * 64 + v * 8);
            }
        } else {
#pragma unroll
            for (int t = 0; t < 2; ++t) {
                int i2 = tid + t * 256;
                int r = i2 >> 2, v = i2 & 3;
                cp16(yb + SWZ(r * 128 + v * 16), Ab + (size_t)r * 64 + v * 8);
            }
        }
    };

    // prologue: weights + Vt + Y(0) in group0, Y(1) in group1
    if (my_iters > 0) {
        if (BR == 1) {
#pragma unroll
            for (int t = 0; t < 8; ++t) {       // Wt1: 256 rows x 8 xfers
                int i2 = tid + t * 256;
                int r = i2 >> 3, v = i2 & 7;
                cp16(sbase + OFF_W + SWZ(r * 128 + v * 16), gWt + (size_t)r * 64 + v * 8);
            }
#pragma unroll
            for (int t = 0; t < 8; ++t) {       // Vt1: 4 chunks x 64 rows x 8 xfers
                int i2 = tid + t * 256;
                int s = i2 >> 9, p = (i2 >> 3) & 63, v = i2 & 7;
                cp16(sbase + OFF_V + s * VCB + SWZ(p * 128 + v * 16),
                     gVt + (size_t)p * 256 + s * 64 + v * 8);
            }
        } else {
#pragma unroll
            for (int t = 0; t < 2; ++t) {       // Wt2: 128 rows x 4 xfers (K=32)
                int i2 = tid + t * 256;
                int r = i2 >> 2, v = i2 & 3;
                cp16(sbase + OFF_W + SWZ(r * 128 + v * 16), gWt + (size_t)r * 64 + v * 8);
            }
#pragma unroll
            for (int t = 0; t < 2; ++t) {       // Vt2: 2 chunks x 32 rows x 8 xfers
                int i2 = tid + t * 256;
                int s = i2 >> 8, p = (i2 >> 3) & 31, v = i2 & 7;
                cp16(sbase + OFF_V + s * VCB + SWZ(p * 128 + v * 16),
                     gVt + (size_t)p * 128 + s * 64 + v * 8);
            }
        }
        issue_y(0);
    }
    cp_commit();
    if (1 < my_iters) issue_y(1);
    cp_commit();

    float oacc[4][ONI][4];
#pragma unroll
    for (int i = 0; i < 4; ++i)
#pragma unroll
        for (int j = 0; j < ONI; ++j)
#pragma unroll
            for (int r = 0; r < 4; ++r) oacc[i][j][r] = 0.f;

    const int a_rowoff = (lane & 7) + ((lane >> 3) & 1) * 8;
    const int a_khalf  = lane >> 4;
    const int laneb    = lane & 15;
    const int b_rowoff = laneb & 7;
    const int b_khalf  = laneb >> 3;

#pragma unroll 1
    for (int j = 0; j < my_iters; ++j) {
        cp_wait1();
        __syncthreads();

        const uint32_t yb = sbase + OFF_Y + (uint32_t)(j & 1) * YB;
        const int tile = t0 + (j / M) * tstr;
        const int rowBase = tile * 128;

#pragma unroll 1
        for (int s = 0; s < NSLAB; ++s) {
            float zacc[4][2][4];
#pragma unroll
            for (int i = 0; i < 4; ++i)
#pragma unroll
                for (int n = 0; n < 2; ++n)
#pragma unroll
                    for (int r = 0; r < 4; ++r) zacc[i][n][r] = 0.f;

            // ---- z slab MMA: Y (128xK) @ Wt rows s*64..s*64+63 ----
#pragma unroll
            for (int ks = 0; ks < KSY; ++ks) {
                const int kbyte = ks * 32;
                uint32_t af[4][4], bf[2][2];
#pragma unroll
                for (int mi = 0; mi < 4; ++mi) {
                    int r = wm * 64 + mi * 16 + a_rowoff;
                    ldsm_x4(af[mi], yb + SWZ(r * 128 + kbyte + a_khalf * 16));
                }
#pragma unroll
                for (int ni = 0; ni < 2; ++ni) {
                    int r = s * 64 + wn * 16 + ni * 8 + b_rowoff;
                    ldsm_x2(bf[ni], sbase + OFF_W + SWZ(r * 128 + kbyte + b_khalf * 16));
                }
#pragma unroll
                for (int mi = 0; mi < 4; ++mi)
#pragma unroll
                    for (int ni = 0; ni < 2; ++ni)
                        mma16816(zacc[mi][ni], af[mi], bf[ni]);
            }

            __syncthreads();   // previous slab's o-MMA reads of zstage done
            // ---- gate + scale, stage bf16 z slab ----
#pragma unroll
            for (int mi = 0; mi < 4; ++mi) {
#pragma unroll
                for (int ni = 0; ni < 2; ++ni) {
                    const int pl = wn * 16 + ni * 8 + (lane & 3) * 2;
#pragma unroll
                    for (int rp = 0; rp < 2; ++rp) {
                        const int lrow = wm * 64 + mi * 16 + (lane >> 2) + rp * 8;
                        float2 g = *(const float2*)(gG + (size_t)(rowBase + lrow) * GDIM
                                                    + GOFSB + s * 64 + pl);
                        __nv_bfloat162 pk;
                        pk.x = __float2bfloat16(zacc[mi][ni][rp * 2]     * g.x * SCALE);
                        pk.y = __float2bfloat16(zacc[mi][ni][rp * 2 + 1] * g.y * SCALE);
                        *(uint32_t*)(dsm + OFF_Z + SWZ(lrow * 128 + pl * 2)) = *(uint32_t*)&pk;
                    }
                }
            }
            __syncthreads();   // z slab staged

            // ---- o MMA: zstage (128x64) @ Vt chunk s, accumulate ----
#pragma unroll
            for (int ks2 = 0; ks2 < 4; ++ks2) {
                const int kbyte = ks2 * 32;
                uint32_t af2[4][4], bfo[ONI][2];
#pragma unroll
                for (int mi = 0; mi < 4; ++mi) {
                    int r = wm * 64 + mi * 16 + a_rowoff;
                    ldsm_x4(af2[mi], sbase + OFF_Z + SWZ(r * 128 + kbyte + a_khalf * 16));
                }
#pragma unroll
                for (int ni = 0; ni < ONI; ++ni) {
                    int rv = wn * (OW / 4) + ni * 8 + b_rowoff;
                    ldsm_x2(bfo[ni], sbase + OFF_V + s * VCB
                                     + SWZ(rv * 128 + kbyte + b_khalf * 16));
                }
#pragma unroll
                for (int mi = 0; mi < 4; ++mi)
#pragma unroll
                    for (int ni = 0; ni < ONI; ++ni)
                        mma16816(oacc[mi][ni], af2[mi], bfo[ni]);
            }
        }

        // ---- store o directly (scales folded; residual handled by combine) ----
        {
            const int mm = j % M;
#pragma unroll
            for (int mi = 0; mi < 4; ++mi) {
#pragma unroll
                for (int ni = 0; ni < ONI; ++ni) {
                    const int p0 = wn * (OW / 4) + ni * 8 + (lane & 3) * 2;
#pragma unroll
                    for (int rp = 0; rp < 2; ++rp) {
                        const int row = rowBase + wm * 64 + mi * 16 + (lane >> 2) + rp * 8;
                        float2 pk = {oacc[mi][ni][rp * 2], oacc[mi][ni][rp * 2 + 1]};
                        *(float2*)(gO + ((size_t)mm * NROWS + row) * OW + p0) = pk;
                        oacc[mi][ni][rp * 2] = 0.f;
                        oacc[mi][ni][rp * 2 + 1] = 0.f;
                    }
                }
            }
        }

        if (j + 2 < my_iters) issue_y(j + 2);
        cp_commit();
    }
}

// ================= final combine: out[:,128:480] = x + ta*gather(o1,o2) ====
__global__ void __launch_bounds__(256) combine_kernel(
    const float* __restrict__ x, const float* __restrict__ alphap,
    float* __restrict__ out)
{
    const int warp = threadIdx.x >> 5;
    const int lane = threadIdx.x & 31;
    const int row  = blockIdx.x * 8 + warp;
    const float ta = tanhf(alphap[0]);
    const float* xr = x + (size_t)row * DIN;
    float* outr = out + (size_t)row * DIN;

#pragma unroll
    for (int t = 0; t < 6; ++t) {          // cols 128..319
        int c = 128 + lane + t * 32;
        int d = c - 128;
        float o = gO1[((size_t)(d % 3) * NROWS + row) * 64 + d / 3];
        outr[c] = xr[c] + ta * o;
    }
#pragma unroll
    for (int t = 0; t < 5; ++t) {          // cols 320..479
        int c = 320 + lane + t * 32;
        int d = c - 320;
        float o = gO2[((size_t)(d % 5) * NROWS + row) * 32 + d / 5];
        outr[c] = xr[c] + ta * o;
    }
}

// ================= launch =================
extern "C" void kernel_launch(void* const* d_in, const int* in_sizes, int n_in,
                              void* d_out, int out_size) {
    const float* x     = (const float*)d_in[0];
    const float* nw0   = (const float*)d_in[1];
    const float* nb0   = (const float*)d_in[2];
    const float* nw1   = (const float*)d_in[3];
    const float* nw2   = (const float*)d_in[4];
    const float* W0    = (const float*)d_in[5];
    const float* b0    = (const float*)d_in[6];
    const float* W1    = (const float*)d_in[7];
    const float* W2    = (const float*)d_in[8];
    const float* V0    = (const float*)d_in[9];
    const float* c0    = (const float*)d_in[10];
    const float* V1    = (const float*)d_in[11];
    const float* V2    = (const float*)d_in[12];
    const float* alpha = (const float*)d_in[13];
    float* out = (float*)d_out;

    constexpr int SM128 = 3 * (128 * 128 + 128 * 128);            // 96 KB
    constexpr int SMZ1  = 256*128 + 4*64*128 + 2*128*128 + 128*128; // 112 KB
    constexpr int SMZ2  = 128*128 + 2*32*128 + 2*128*128 + 128*128; //  72 KB
    cudaFuncSetAttribute(mma_kernel<128, 128, 0>, cudaFuncAttributeMaxDynamicSharedMemorySize, SM128);
    cudaFuncSetAttribute(mma_kernel<512, 128, 3>, cudaFuncAttributeMaxDynamicSharedMemorySize, SM128);
    cudaFuncSetAttribute(zo_kernel<3, 1>, cudaFuncAttributeMaxDynamicSharedMemorySize, SMZ1);
    cudaFuncSetAttribute(zo_kernel<5, 2>, cudaFuncAttributeMaxDynamicSharedMemorySize, SMZ2);

    convert_w<<<880, 256>>>(W0, W1, W2, V0, V1, V2);
    norm_kernel<<<NROWS / 8, 256>>>(x, nw0, nb0, nw1, nw2);

    // stage 1: h0 -> silu/gates
    mma_kernel<128, 128, 0><<<dim3(84, 7, 1), 256, SM128>>>(b0, nullptr, nullptr, nullptr);
    // fused z+down per branch
    zo_kernel<3, 1><<<256, 256, SMZ1>>>();
    zo_kernel<5, 2><<<256, 256, SMZ2>>>();
    // o0 down-projection with residual
    mma_kernel<512, 128, 3><<<dim3(296, 1, 1), 256, SM128>>>(c0, x, alpha, out);
    // residual gather for cols 128..479
    combine_kernel<<<NROWS / 8, 256>>>(x, alpha, out);
}

// round 12
// speedup vs baseline: 4.0901x; 1.0903x over previous
#include <cuda_runtime.h>
#include <cuda_bf16.h>
#include <math.h>
#include <cstdint>

#define NROWS 65536
#define DIN   480
#define H0D   512
#define GDIM  384

// ================= scratch (device globals; no allocation) =================
__device__ __nv_bfloat16 gY0b[(size_t)NROWS * 128];       // y0 /sqrt(128)
__device__ __nv_bfloat16 gY1b[(size_t)3 * NROWS * 64];    // [m][row][64]
__device__ __nv_bfloat16 gY2b[(size_t)5 * NROWS * 64];    // [m][row][64] (only k<32 used)
__device__ __nv_bfloat16 gSb [(size_t)NROWS * 512];       // silu(h0)/sqrt(512)
// gates in MMA-native layout: [sg 0..5][tile 0..511][wid 0..7][idx16 0..15][lane 0..31] float2
__device__ float         gG3 [(size_t)6 * 512 * 128 * 64];
__device__ float         gO1 [(size_t)3 * NROWS * 64];    // o1 (scales folded)
__device__ float         gO2 [(size_t)5 * NROWS * 32];    // o2
// transposed bf16 weights  Wt[p][k]
__device__ __nv_bfloat16 gWt0[(size_t)896 * 128];
__device__ __nv_bfloat16 gWt1[(size_t)256 * 64];
__device__ __nv_bfloat16 gWt2[(size_t)128 * 64];          // k 32..63 zero (unused)
__device__ __nv_bfloat16 gVt0[(size_t)128 * 512];
__device__ __nv_bfloat16 gVt1[(size_t)64 * 256];
__device__ __nv_bfloat16 gVt2[(size_t)32 * 128];

// ================= helpers =================
__device__ __forceinline__ uint32_t smem_to_u32(const void* p) {
    uint32_t a;
    asm("{ .reg .u64 t; cvta.to.shared.u64 t, %1; cvt.u32.u64 %0, t; }" : "=r"(a) : "l"(p));
    return a;
}
#define SWZ(b) ((b) ^ (((b) >> 3) & 0x70))

__device__ __forceinline__ void cp16(uint32_t saddr, const void* g) {
    asm volatile("cp.async.cg.shared.global [%0], [%1], 16;" :: "r"(saddr), "l"(g));
}
__device__ __forceinline__ void cp_commit() {
    asm volatile("cp.async.commit_group;" ::: "memory");
}
__device__ __forceinline__ void cp_wait2() {
    asm volatile("cp.async.wait_group 2;" ::: "memory");
}
__device__ __forceinline__ void cp_wait1() {
    asm volatile("cp.async.wait_group 1;" ::: "memory");
}
__device__ __forceinline__ void prefetch_l1(const void* p) {
    asm volatile("prefetch.global.L1 [%0];" :: "l"(p));
}

__device__ __forceinline__ void ldsm_x4(uint32_t* r, uint32_t addr) {
    asm volatile("ldmatrix.sync.aligned.m8n8.x4.shared.b16 {%0,%1,%2,%3}, [%4];"
        : "=r"(r[0]), "=r"(r[1]), "=r"(r[2]), "=r"(r[3]) : "r"(addr));
}
__device__ __forceinline__ void ldsm_x2(uint32_t* r, uint32_t addr) {
    asm volatile("ldmatrix.sync.aligned.m8n8.x2.shared.b16 {%0,%1}, [%2];"
        : "=r"(r[0]), "=r"(r[1]) : "r"(addr));
}
__device__ __forceinline__ void mma16816(float* d, const uint32_t* a, const uint32_t* b) {
    asm volatile(
        "mma.sync.aligned.m16n8k16.row.col.f32.bf16.bf16.f32 "
        "{%0,%1,%2,%3}, {%4,%5,%6,%7}, {%8,%9}, {%0,%1,%2,%3};"
        : "+f"(d[0]), "+f"(d[1]), "+f"(d[2]), "+f"(d[3])
        : "r"(a[0]), "r"(a[1]), "r"(a[2]), "r"(a[3]), "r"(b[0]), "r"(b[1]));
}
__device__ __forceinline__ float sigmf(float v) { return 1.0f / (1.0f + __expf(-v)); }

// ================= kernel 0: weight convert+transpose =================
__global__ void __launch_bounds__(256) convert_w(
    const float* __restrict__ W0, const float* __restrict__ W1, const float* __restrict__ W2,
    const float* __restrict__ V0, const float* __restrict__ V1, const float* __restrict__ V2)
{
    int i = blockIdx.x * 256 + threadIdx.x;
    if (i < 114688) {                       // Wt0[896][128] <- W0[128][896]
        int p = i / 128, k = i % 128;
        gWt0[i] = __float2bfloat16(W0[k * 896 + p]);
    } else if ((i -= 114688) < 16384) {     // Wt1[256][64] <- W1[64][256]
        int p = i / 64, k = i % 64;
        gWt1[i] = __float2bfloat16(W1[k * 256 + p]);
    } else if ((i -= 16384) < 8192) {       // Wt2[128][64] <- W2[32][128], pad
        int p = i / 64, k = i % 64;
        gWt2[i] = (k < 32) ? __float2bfloat16(W2[k * 128 + p]) : __float2bfloat16(0.f);
    } else if ((i -= 8192) < 65536) {       // Vt0[128][512] <- V0[512][128]
        int p = i / 512, k = i % 512;
        gVt0[i] = __float2bfloat16(V0[k * 128 + p]);
    } else if ((i -= 65536) < 16384) {      // Vt1[64][256] <- V1[256][64]
        int p = i / 256, k = i % 256;
        gVt1[i] = __float2bfloat16(V1[k * 64 + p]);
    } else if ((i -= 16384) < 4096) {       // Vt2[32][128] <- V2[128][32]
        int p = i / 128, k = i % 128;
        gVt2[i] = __float2bfloat16(V2[k * 32 + p]);
    }
}

// ================= kernel 1: norms (one warp per row) =================
__global__ void __launch_bounds__(256) norm_kernel(
    const float* __restrict__ x,  const float* __restrict__ nw0,
    const float* __restrict__ nb0, const float* __restrict__ nw1,
    const float* __restrict__ nw2)
{
    const int warp = threadIdx.x >> 5;
    const int lane = threadIdx.x & 31;
    const int row  = blockIdx.x * 8 + warp;
    const float* xr = x + (size_t)row * DIN;

    float4 v0 = ((const float4*)xr)[lane];
    float s = v0.x + v0.y + v0.z + v0.w;
    float q = v0.x*v0.x + v0.y*v0.y + v0.z*v0.z + v0.w*v0.w;
#pragma unroll
    for (int o = 16; o; o >>= 1) {
        s += __shfl_xor_sync(0xffffffffu, s, o);
        q += __shfl_xor_sync(0xffffffffu, q, o);
    }
    const float mu   = s * (1.0f / 128.0f);
    const float rstd = rsqrtf(q * (1.0f / 128.0f) - mu * mu + 1e-8f);

    float ss1 = 0.f, ss2 = 0.f;
    const float4* xr2 = (const float4*)(xr + 128);
#pragma unroll
    for (int j = lane; j < 88; j += 32) {
        float4 v = xr2[j];
        float d = v.x*v.x + v.y*v.y + v.z*v.z + v.w*v.w;
        if (j < 48) ss1 += d; else ss2 += d;
    }
#pragma unroll
    for (int o = 16; o; o >>= 1) {
        ss1 += __shfl_xor_sync(0xffffffffu, ss1, o);
        ss2 += __shfl_xor_sync(0xffffffffu, ss2, o);
    }
    const float inv = rsqrtf(0.5f * (ss1 * (1.f/192.f) + ss2 * (1.f/160.f)) + 1e-8f);

    const float invS0 = 0.08838834764831845f;
    float4 w = ((const float4*)nw0)[lane];
    float4 b = ((const float4*)nb0)[lane];
    __nv_bfloat16* y0 = gY0b + (size_t)row * 128 + lane * 4;
    y0[0] = __float2bfloat16(((v0.x - mu) * rstd * w.x + b.x) * invS0);
    y0[1] = __float2bfloat16(((v0.y - mu) * rstd * w.y + b.y) * invS0);
    y0[2] = __float2bfloat16(((v0.z - mu) * rstd * w.z + b.z) * invS0);
    y0[3] = __float2bfloat16(((v0.w - mu) * rstd * w.w + b.w) * invS0);

#pragma unroll
    for (int t = 0; t < 2; ++t) {
        int u = lane + t * 32;
        float c = inv * nw1[u] * 0.125f;
#pragma unroll
        for (int m = 0; m < 3; ++m)
            gY1b[((size_t)m * NROWS + row) * 64 + u] = __float2bfloat16(xr[128 + 3*u + m] * c);
    }
    {
        int u = lane;
        float c = inv * nw2[u] * 0.17677669529663689f;
#pragma unroll
        for (int m = 0; m < 5; ++m)
            gY2b[((size_t)m * NROWS + row) * 64 + u] =
                __float2bfloat16(xr[320 + 5*u + m] * c);
    }
}

// ================= HMMA GEMM, persistent CTAs + cp.async pipeline =================
// EPI 0: h0 -> silu/gate ; EPI 3: o0 with residual.
template<int KdA, int NT, int EPI>
__global__ void __launch_bounds__(256, 2) mma_kernel(
    const float* __restrict__ bias, const float* __restrict__ X,
    const float* __restrict__ alphap, float* __restrict__ Out)
{
    constexpr int NCH   = KdA / 64;
    constexpr int WT_N  = NT / 4;
    constexpr int NI    = WT_N / 8;
    constexpr int MI    = 4;
    constexpr int SAB   = 128 * 128;
    constexpr int SBB   = NT * 128;
    constexpr int STAGE = SAB + SBB;
    constexpr int DEPTH = 3;
    constexpr int NTILES = NROWS / 128;

    extern __shared__ __align__(16) char dsm[];
    const uint32_t sbase = smem_to_u32(dsm);

    const int tid  = threadIdx.x;
    const int wid  = tid >> 5;
    const int lane = tid & 31;
    const int wm   = wid >> 2;
    const int wn   = wid & 3;
    const int pb   = blockIdx.y * NT;
    const int t0   = blockIdx.x;
    const int tstr = gridDim.x;

    const __nv_bfloat16* gA  = (EPI == 0) ? gY0b : gSb;
    const __nv_bfloat16* gBw = (EPI == 0) ? gWt0 : gVt0;

    const int my_tiles = (t0 < NTILES) ? ((NTILES - 1 - t0) / tstr + 1) : 0;
    const int my_iters = my_tiles * NCH;

    auto issue_load = [&](int idx) {
        const int tile = t0 + (idx / NCH) * tstr;
        const int ch   = idx % NCH;
        const uint32_t st = sbase + (uint32_t)(idx % DEPTH) * STAGE;
        const __nv_bfloat16* Ab = gA + (size_t)(tile * 128) * KdA + ch * 64;
#pragma unroll
        for (int t = 0; t < 4; ++t) {
            int i2 = tid + t * 256;
            int r = i2 >> 3, v = i2 & 7;
            cp16(st + SWZ(r * 128 + v * 16), Ab + (size_t)r * KdA + v * 8);
        }
        const __nv_bfloat16* Bb = gBw + (size_t)pb * KdA + ch * 64;
#pragma unroll
        for (int t = 0; t < NT / 32; ++t) {
            int i2 = tid + t * 256;
            int r = i2 >> 3, v = i2 & 7;
            cp16(st + SAB + SWZ(r * 128 + v * 16), Bb + (size_t)r * KdA + v * 8);
        }
    };

    float acc[MI][NI][4];
#pragma unroll
    for (int i = 0; i < MI; ++i)
#pragma unroll
        for (int j = 0; j < NI; ++j)
#pragma unroll
            for (int r = 0; r < 4; ++r) acc[i][j][r] = 0.f;

    const int a_rowoff = (lane & 7) + ((lane >> 3) & 1) * 8;
    const int a_khalf  = lane >> 4;
    const int laneb    = lane & 15;
    const int b_rowoff = laneb & 7;
    const int b_khalf  = laneb >> 3;
    const float ta = (EPI == 3) ? tanhf(alphap[0]) : 0.0f;

#pragma unroll
    for (int i = 0; i < DEPTH; ++i) {
        if (i < my_iters) issue_load(i);
        cp_commit();
    }

#pragma unroll 1
    for (int it = 0; it < my_iters; ++it) {
        cp_wait2();
        __syncthreads();

        const uint32_t st = sbase + (uint32_t)(it % DEPTH) * STAGE;
#pragma unroll
        for (int ks = 0; ks < 4; ++ks) {
            const int kbyte = ks * 32;
            uint32_t af[MI][4], bf[NI][2];
#pragma unroll
            for (int mi = 0; mi < MI; ++mi) {
                int r = wm * 64 + mi * 16 + a_rowoff;
                ldsm_x4(af[mi], st + SWZ(r * 128 + kbyte + a_khalf * 16));
            }
#pragma unroll
            for (int ni = 0; ni < NI; ++ni) {
                int r = wn * WT_N + ni * 8 + b_rowoff;
                ldsm_x2(bf[ni], st + SAB + SWZ(r * 128 + kbyte + b_khalf * 16));
            }
#pragma unroll
            for (int mi = 0; mi < MI; ++mi)
#pragma unroll
                for (int ni = 0; ni < NI; ++ni)
                    mma16816(acc[mi][ni], af[mi], bf[ni]);
        }

        if ((it % NCH) == NCH - 1) {
            const int tile = t0 + (it / NCH) * tstr;
            const int rowBase = tile * 128;
#pragma unroll
            for (int mi = 0; mi < MI; ++mi) {
#pragma unroll
                for (int ni = 0; ni < NI; ++ni) {
                    const int p0 = pb + wn * WT_N + ni * 8 + (lane & 3) * 2;
#pragma unroll
                    for (int rp = 0; rp < 2; ++rp) {
                        const int row = rowBase + wm * 64 + mi * 16 + (lane >> 2) + rp * 8;
                        float v0 = acc[mi][ni][rp * 2];
                        float v1 = acc[mi][ni][rp * 2 + 1];
                        if (EPI == 0) {
                            float h0 = v0 + bias[p0];
                            float h1 = v1 + bias[p0 + 1];
                            if (p0 < H0D) {   // uniform per block
                                __nv_bfloat162 pk;
                                pk.x = __float2bfloat16(h0 * sigmf(h0) * 0.04419417382415922f);
                                pk.y = __float2bfloat16(h1 * sigmf(h1) * 0.04419417382415922f);
                                *(__nv_bfloat162*)(gSb + (size_t)row * 512 + p0) = pk;
                            } else {
                                // gate -> MMA-native layout for zo consumers
                                float2 pk = {sigmf(h0), sigmf(h1)};
                                int gcol = p0 - H0D;
                                int sg = gcol >> 6, pl = gcol & 63;
                                int lr = row & 127;
                                int wm_z = lr >> 6, mi_z = (lr >> 4) & 3,
                                    rp_z = (lr >> 3) & 1, lq = lr & 7;
                                int wn_z = pl >> 4, ni_z = (pl >> 3) & 1,
                                    l2 = (pl >> 1) & 3;
                                int wid_z = wm_z * 4 + wn_z;
                                int lane_z = lq * 4 + l2;
                                int idx = mi_z * 4 + ni_z * 2 + rp_z;
                                size_t off = (((size_t)sg * NTILES + tile) << 13)
                                           + wid_z * 1024 + (idx * 32 + lane_z) * 2;
                                *(float2*)(gG3 + off) = pk;
                            }
                        } else {
                            size_t o = (size_t)row * DIN + p0;
                            float2 xv = *(const float2*)(X + o);
                            float2 pk = {xv.x + ta * (v0 + bias[p0]),
                                         xv.y + ta * (v1 + bias[p0 + 1])};
                            *(float2*)(Out + o) = pk;
                        }
                        acc[mi][ni][rp * 2] = 0.f;
                        acc[mi][ni][rp * 2 + 1] = 0.f;
                    }
                }
            }
        }

        __syncthreads();
        if (it + DEPTH < my_iters) issue_load(it + DEPTH);
        cp_commit();
    }
}

// ================= fused z + down-projection per spectral branch =================
// For each (row tile, m): loop H in 64-col slabs s:
//   z_s = Y[m] @ Wt-slab-s ; stage bf16(z_s * g * scale) in smem ;
//   o  += z_s @ Vt-chunk-s   (k-chunk order s=0..NSLAB-1)
// gates read from gG3 (MMA-native layout -> fully coalesced).
template<int M, int BR>   // BR=1: H=256,K=64 ; BR=2: H=128,K=32
__global__ void __launch_bounds__(256, 2) zo_kernel()
{
    constexpr int NSLAB  = (BR == 1) ? 4 : 2;       // H / 64
    constexpr int KSY    = (BR == 1) ? 4 : 2;       // k16 steps of the z GEMM
    constexpr int OW     = (BR == 1) ? 64 : 32;     // o columns
    constexpr int ONI    = OW / 32;                 // 2 / 1
    constexpr int SGOF   = (BR == 1) ? 0 : 4;       // global gate-slab offset
    constexpr int WROWS  = (BR == 1) ? 256 : 128;
    constexpr int VROWS  = OW;
    constexpr int VCB    = VROWS * 128;             // bytes per Vt chunk
    constexpr int OFF_W  = 0;
    constexpr int OFF_V  = OFF_W + WROWS * 128;
    constexpr int OFF_Y  = OFF_V + NSLAB * VCB;
    constexpr int YB     = 128 * 128;
    constexpr int OFF_Z  = OFF_Y + 2 * YB;
    constexpr int NTILES = NROWS / 128;

    extern __shared__ __align__(16) char dsm[];
    const uint32_t sbase = smem_to_u32(dsm);

    const int tid  = threadIdx.x;
    const int wid  = tid >> 5;
    const int lane = tid & 31;
    const int wm   = wid >> 2;
    const int wn   = wid & 3;
    const int t0   = blockIdx.x;
    const int tstr = gridDim.x;

    const __nv_bfloat16* gA  = (BR == 1) ? gY1b : gY2b;
    const __nv_bfloat16* gWt = (BR == 1) ? gWt1 : gWt2;
    const __nv_bfloat16* gVt = (BR == 1) ? gVt1 : gVt2;
    float* gO = (BR == 1) ? gO1 : gO2;
    const float SCALE = (BR == 1) ? 0.0625f : 0.08838834764831845f;

    const int my_tiles = (t0 < NTILES) ? ((NTILES - 1 - t0) / tstr + 1) : 0;
    const int my_iters = my_tiles * M;

    auto issue_y = [&](int j) {
        const int tile = t0 + (j / M) * tstr;
        const int mm   = j % M;
        const __nv_bfloat16* Ab = gA + ((size_t)mm * NROWS + tile * 128) * 64;
        const uint32_t yb = sbase + OFF_Y + (uint32_t)(j & 1) * YB;
        if (KSY == 4) {
#pragma unroll
            for (int t = 0; t < 4; ++t) {
                int i2 = tid + t * 256;
                int r = i2 >> 3, v = i2 & 7;
                cp16(yb + SWZ(r * 128 + v * 16), Ab + (size_t)r * 64 + v * 8);
            }
        } else {
#pragma unroll
            for (int t = 0; t < 2; ++t) {
                int i2 = tid + t * 256;
                int r = i2 >> 2, v = i2 & 3;
                cp16(yb + SWZ(r * 128 + v * 16), Ab + (size_t)r * 64 + v * 8);
            }
        }
    };

    // prologue: weights + Vt + Y(0) in group0, Y(1) in group1
    if (my_iters > 0) {
        if (BR == 1) {
#pragma unroll
            for (int t = 0; t < 8; ++t) {       // Wt1: 256 rows x 8 xfers
                int i2 = tid + t * 256;
                int r = i2 >> 3, v = i2 & 7;
                cp16(sbase + OFF_W + SWZ(r * 128 + v * 16), gWt + (size_t)r * 64 + v * 8);
            }
#pragma unroll
            for (int t = 0; t < 8; ++t) {       // Vt1: 4 chunks x 64 rows x 8 xfers
                int i2 = tid + t * 256;
                int s = i2 >> 9, p = (i2 >> 3) & 63, v = i2 & 7;
                cp16(sbase + OFF_V + s * VCB + SWZ(p * 128 + v * 16),
                     gVt + (size_t)p * 256 + s * 64 + v * 8);
            }
        } else {
#pragma unroll
            for (int t = 0; t < 2; ++t) {       // Wt2: 128 rows x 4 xfers (K=32)
                int i2 = tid + t * 256;
                int r = i2 >> 2, v = i2 & 3;
                cp16(sbase + OFF_W + SWZ(r * 128 + v * 16), gWt + (size_t)r * 64 + v * 8);
            }
#pragma unroll
            for (int t = 0; t < 2; ++t) {       // Vt2: 2 chunks x 32 rows x 8 xfers
                int i2 = tid + t * 256;
                int s = i2 >> 8, p = (i2 >> 3) & 31, v = i2 & 7;
                cp16(sbase + OFF_V + s * VCB + SWZ(p * 128 + v * 16),
                     gVt + (size_t)p * 128 + s * 64 + v * 8);
            }
        }
        issue_y(0);
    }
    cp_commit();
    if (1 < my_iters) issue_y(1);
    cp_commit();

    float oacc[4][ONI][4];
#pragma unroll
    for (int i = 0; i < 4; ++i)
#pragma unroll
        for (int j = 0; j < ONI; ++j)
#pragma unroll
            for (int r = 0; r < 4; ++r) oacc[i][j][r] = 0.f;

    const int a_rowoff = (lane & 7) + ((lane >> 3) & 1) * 8;
    const int a_khalf  = lane >> 4;
    const int laneb    = lane & 15;
    const int b_rowoff = laneb & 7;
    const int b_khalf  = laneb >> 3;

#pragma unroll 1
    for (int j = 0; j < my_iters; ++j) {
        cp_wait1();
        __syncthreads();

        const uint32_t yb = sbase + OFF_Y + (uint32_t)(j & 1) * YB;
        const int tile = t0 + (j / M) * tstr;
        const int rowBase = tile * 128;

#pragma unroll 1
        for (int s = 0; s < NSLAB; ++s) {
            // gate block for this slab: gG3[(SGOF+s)*NTILES + tile], warp's 4KB region
            const size_t gblk = ((size_t)(SGOF + s) * NTILES + tile) << 13;  // floats
            const float2* Gt = (const float2*)(gG3 + gblk) + wid * 512 + lane;
            prefetch_l1((const char*)(gG3 + gblk) + wid * 4096 + lane * 128);

            float zacc[4][2][4];
#pragma unroll
            for (int i = 0; i < 4; ++i)
#pragma unroll
                for (int n = 0; n < 2; ++n)
#pragma unroll
                    for (int r = 0; r < 4; ++r) zacc[i][n][r] = 0.f;

            // ---- z slab MMA: Y (128xK) @ Wt rows s*64..s*64+63 ----
#pragma unroll
            for (int ks = 0; ks < KSY; ++ks) {
                const int kbyte = ks * 32;
                uint32_t af[4][4], bf[2][2];
#pragma unroll
                for (int mi = 0; mi < 4; ++mi) {
                    int r = wm * 64 + mi * 16 + a_rowoff;
                    ldsm_x4(af[mi], yb + SWZ(r * 128 + kbyte + a_khalf * 16));
                }
#pragma unroll
                for (int ni = 0; ni < 2; ++ni) {
                    int r = s * 64 + wn * 16 + ni * 8 + b_rowoff;
                    ldsm_x2(bf[ni], sbase + OFF_W + SWZ(r * 128 + kbyte + b_khalf * 16));
                }
#pragma unroll
                for (int mi = 0; mi < 4; ++mi)
#pragma unroll
                    for (int ni = 0; ni < 2; ++ni)
                        mma16816(zacc[mi][ni], af[mi], bf[ni]);
            }

            __syncthreads();   // previous slab's o-MMA reads of zstage done
            // ---- gate + scale, stage bf16 z slab (coalesced gate loads) ----
#pragma unroll
            for (int mi = 0; mi < 4; ++mi) {
#pragma unroll
                for (int ni = 0; ni < 2; ++ni) {
                    const int pl = wn * 16 + ni * 8 + (lane & 3) * 2;
#pragma unroll
                    for (int rp = 0; rp < 2; ++rp) {
                        const int lrow = wm * 64 + mi * 16 + (lane >> 2) + rp * 8;
                        float2 g = Gt[(mi * 4 + ni * 2 + rp) * 32];
                        __nv_bfloat162 pk;
                        pk.x = __float2bfloat16(zacc[mi][ni][rp * 2]     * g.x * SCALE);
                        pk.y = __float2bfloat16(zacc[mi][ni][rp * 2 + 1] * g.y * SCALE);
                        *(uint32_t*)(dsm + OFF_Z + SWZ(lrow * 128 + pl * 2)) = *(uint32_t*)&pk;
                    }
                }
            }
            __syncthreads();   // z slab staged

            // ---- o MMA: zstage (128x64) @ Vt chunk s, accumulate ----
#pragma unroll
            for (int ks2 = 0; ks2 < 4; ++ks2) {
                const int kbyte = ks2 * 32;
                uint32_t af2[4][4], bfo[ONI][2];
#pragma unroll
                for (int mi = 0; mi < 4; ++mi) {
                    int r = wm * 64 + mi * 16 + a_rowoff;
                    ldsm_x4(af2[mi], sbase + OFF_Z + SWZ(r * 128 + kbyte + a_khalf * 16));
                }
#pragma unroll
                for (int ni = 0; ni < ONI; ++ni) {
                    int rv = wn * (OW / 4) + ni * 8 + b_rowoff;
                    ldsm_x2(bfo[ni], sbase + OFF_V + s * VCB
                                     + SWZ(rv * 128 + kbyte + b_khalf * 16));
                }
#pragma unroll
                for (int mi = 0; mi < 4; ++mi)
#pragma unroll
                    for (int ni = 0; ni < ONI; ++ni)
                        mma16816(oacc[mi][ni], af2[mi], bfo[ni]);
            }
        }

        // ---- store o directly (scales folded; residual handled by combine) ----
        {
            const int mm = j % M;
#pragma unroll
            for (int mi = 0; mi < 4; ++mi) {
#pragma unroll
                for (int ni = 0; ni < ONI; ++ni) {
                    const int p0 = wn * (OW / 4) + ni * 8 + (lane & 3) * 2;
#pragma unroll
                    for (int rp = 0; rp < 2; ++rp) {
                        const int row = rowBase + wm * 64 + mi * 16 + (lane >> 2) + rp * 8;
                        float2 pk = {oacc[mi][ni][rp * 2], oacc[mi][ni][rp * 2 + 1]};
                        *(float2*)(gO + ((size_t)mm * NROWS + row) * OW + p0) = pk;
                        oacc[mi][ni][rp * 2] = 0.f;
                        oacc[mi][ni][rp * 2 + 1] = 0.f;
                    }
                }
            }
        }

        if (j + 2 < my_iters) issue_y(j + 2);
        cp_commit();
    }
}

// ================= final combine: out[:,128:480] = x + ta*gather(o1,o2) ====
__global__ void __launch_bounds__(256) combine_kernel(
    const float* __restrict__ x, const float* __restrict__ alphap,
    float* __restrict__ out)
{
    const int warp = threadIdx.x >> 5;
    const int lane = threadIdx.x & 31;
    const int row  = blockIdx.x * 8 + warp;
    const float ta = tanhf(alphap[0]);
    const float* xr = x + (size_t)row * DIN;
    float* outr = out + (size_t)row * DIN;

#pragma unroll
    for (int t = 0; t < 6; ++t) {          // cols 128..319
        int c = 128 + lane + t * 32;
        int d = c - 128;
        float o = gO1[((size_t)(d % 3) * NROWS + row) * 64 + d / 3];
        outr[c] = xr[c] + ta * o;
    }
#pragma unroll
    for (int t = 0; t < 5; ++t) {          // cols 320..479
        int c = 320 + lane + t * 32;
        int d = c - 320;
        float o = gO2[((size_t)(d % 5) * NROWS + row) * 32 + d / 5];
        outr[c] = xr[c] + ta * o;
    }
}

// ================= launch =================
extern "C" void kernel_launch(void* const* d_in, const int* in_sizes, int n_in,
                              void* d_out, int out_size) {
    const float* x     = (const float*)d_in[0];
    const float* nw0   = (const float*)d_in[1];
    const float* nb0   = (const float*)d_in[2];
    const float* nw1   = (const float*)d_in[3];
    const float* nw2   = (const float*)d_in[4];
    const float* W0    = (const float*)d_in[5];
    const float* b0    = (const float*)d_in[6];
    const float* W1    = (const float*)d_in[7];
    const float* W2    = (const float*)d_in[8];
    const float* V0    = (const float*)d_in[9];
    const float* c0    = (const float*)d_in[10];
    const float* V1    = (const float*)d_in[11];
    const float* V2    = (const float*)d_in[12];
    const float* alpha = (const float*)d_in[13];
    float* out = (float*)d_out;

    constexpr int SM128 = 3 * (128 * 128 + 128 * 128);              // 96 KB
    constexpr int SMZ1  = 256*128 + 4*64*128 + 2*128*128 + 128*128; // 112 KB
    constexpr int SMZ2  = 128*128 + 2*32*128 + 2*128*128 + 128*128; //  72 KB
    cudaFuncSetAttribute(mma_kernel<128, 128, 0>, cudaFuncAttributeMaxDynamicSharedMemorySize, SM128);
    cudaFuncSetAttribute(mma_kernel<512, 128, 3>, cudaFuncAttributeMaxDynamicSharedMemorySize, SM128);
    cudaFuncSetAttribute(zo_kernel<3, 1>, cudaFuncAttributeMaxDynamicSharedMemorySize, SMZ1);
    cudaFuncSetAttribute(zo_kernel<5, 2>, cudaFuncAttributeMaxDynamicSharedMemorySize, SMZ2);

    convert_w<<<880, 256>>>(W0, W1, W2, V0, V1, V2);
    norm_kernel<<<NROWS / 8, 256>>>(x, nw0, nb0, nw1, nw2);

    // stage 1: h0 -> silu/gates
    mma_kernel<128, 128, 0><<<dim3(84, 7, 1), 256, SM128>>>(b0, nullptr, nullptr, nullptr);
    // fused z+down per branch
    zo_kernel<3, 1><<<296, 256, SMZ1>>>();
    zo_kernel<5, 2><<<296, 256, SMZ2>>>();
    // o0 down-projection with residual
    mma_kernel<512, 128, 3><<<dim3(296, 1, 1), 256, SM128>>>(c0, x, alpha, out);
    // residual gather for cols 128..479
    combine_kernel<<<NROWS / 8, 256>>>(x, alpha, out);
}

// round 13
// speedup vs baseline: 4.3168x; 1.0554x over previous
#include <cuda_runtime.h>
#include <cuda_bf16.h>
#include <math.h>
#include <cstdint>

#define NROWS 65536
#define DIN   480
#define H0D   512
#define GDIM  384
#define TAILG 296

// ================= scratch (device globals; no allocation) =================
__device__ __nv_bfloat16 gY0b[(size_t)NROWS * 128];       // y0 /sqrt(128)
__device__ __nv_bfloat16 gY1b[(size_t)3 * NROWS * 64];    // [m][row][64]
__device__ __nv_bfloat16 gY2b[(size_t)5 * NROWS * 64];    // [m][row][64] (only k<32 used)
__device__ __nv_bfloat16 gSb [(size_t)NROWS * 512];       // silu(h0)/sqrt(512)
// gates in MMA-native layout: [sg 0..5][tile 0..511][wid 0..7][idx16 0..15][lane 0..31] float2
__device__ float         gG3 [(size_t)6 * 512 * 128 * 64];
__device__ float         gO1 [(size_t)3 * NROWS * 64];    // o1 (scales folded)
__device__ float         gO2 [(size_t)5 * NROWS * 32];    // o2
// transposed bf16 weights  Wt[p][k]
__device__ __nv_bfloat16 gWt0[(size_t)896 * 128];
__device__ __nv_bfloat16 gWt1[(size_t)256 * 64];
__device__ __nv_bfloat16 gWt2[(size_t)128 * 64];          // k 32..63 zero (unused)
__device__ __nv_bfloat16 gVt0[(size_t)128 * 512];
__device__ __nv_bfloat16 gVt1[(size_t)64 * 256];
__device__ __nv_bfloat16 gVt2[(size_t)32 * 128];

// ================= helpers =================
__device__ __forceinline__ uint32_t smem_to_u32(const void* p) {
    uint32_t a;
    asm("{ .reg .u64 t; cvta.to.shared.u64 t, %1; cvt.u32.u64 %0, t; }" : "=r"(a) : "l"(p));
    return a;
}
#define SWZ(b) ((b) ^ (((b) >> 3) & 0x70))

__device__ __forceinline__ void cp16(uint32_t saddr, const void* g) {
    asm volatile("cp.async.cg.shared.global [%0], [%1], 16;" :: "r"(saddr), "l"(g));
}
__device__ __forceinline__ void cp_commit() {
    asm volatile("cp.async.commit_group;" ::: "memory");
}
__device__ __forceinline__ void cp_wait2() {
    asm volatile("cp.async.wait_group 2;" ::: "memory");
}
__device__ __forceinline__ void cp_wait1() {
    asm volatile("cp.async.wait_group 1;" ::: "memory");
}
__device__ __forceinline__ void prefetch_l1(const void* p) {
    asm volatile("prefetch.global.L1 [%0];" :: "l"(p));
}

__device__ __forceinline__ void ldsm_x4(uint32_t* r, uint32_t addr) {
    asm volatile("ldmatrix.sync.aligned.m8n8.x4.shared.b16 {%0,%1,%2,%3}, [%4];"
        : "=r"(r[0]), "=r"(r[1]), "=r"(r[2]), "=r"(r[3]) : "r"(addr));
}
__device__ __forceinline__ void ldsm_x2(uint32_t* r, uint32_t addr) {
    asm volatile("ldmatrix.sync.aligned.m8n8.x2.shared.b16 {%0,%1}, [%2];"
        : "=r"(r[0]), "=r"(r[1]) : "r"(addr));
}
__device__ __forceinline__ void mma16816(float* d, const uint32_t* a, const uint32_t* b) {
    asm volatile(
        "mma.sync.aligned.m16n8k16.row.col.f32.bf16.bf16.f32 "
        "{%0,%1,%2,%3}, {%4,%5,%6,%7}, {%8,%9}, {%0,%1,%2,%3};"
        : "+f"(d[0]), "+f"(d[1]), "+f"(d[2]), "+f"(d[3])
        : "r"(a[0]), "r"(a[1]), "r"(a[2]), "r"(a[3]), "r"(b[0]), "r"(b[1]));
}
__device__ __forceinline__ float sigmf(float v) { return 1.0f / (1.0f + __expf(-v)); }

// ================= kernel 0: weight convert+transpose =================
__global__ void __launch_bounds__(256) convert_w(
    const float* __restrict__ W0, const float* __restrict__ W1, const float* __restrict__ W2,
    const float* __restrict__ V0, const float* __restrict__ V1, const float* __restrict__ V2)
{
    int i = blockIdx.x * 256 + threadIdx.x;
    if (i < 114688) {                       // Wt0[896][128] <- W0[128][896]
        int p = i / 128, k = i % 128;
        gWt0[i] = __float2bfloat16(W0[k * 896 + p]);
    } else if ((i -= 114688) < 16384) {     // Wt1[256][64] <- W1[64][256]
        int p = i / 64, k = i % 64;
        gWt1[i] = __float2bfloat16(W1[k * 256 + p]);
    } else if ((i -= 16384) < 8192) {       // Wt2[128][64] <- W2[32][128], pad
        int p = i / 64, k = i % 64;
        gWt2[i] = (k < 32) ? __float2bfloat16(W2[k * 128 + p]) : __float2bfloat16(0.f);
    } else if ((i -= 8192) < 65536) {       // Vt0[128][512] <- V0[512][128]
        int p = i / 512, k = i % 512;
        gVt0[i] = __float2bfloat16(V0[k * 128 + p]);
    } else if ((i -= 65536) < 16384) {      // Vt1[64][256] <- V1[256][64]
        int p = i / 256, k = i % 256;
        gVt1[i] = __float2bfloat16(V1[k * 64 + p]);
    } else if ((i -= 16384) < 4096) {       // Vt2[32][128] <- V2[128][32]
        int p = i / 128, k = i % 128;
        gVt2[i] = __float2bfloat16(V2[k * 32 + p]);
    }
}

// ================= kernel 1: norms (one warp per row) =================
__global__ void __launch_bounds__(256) norm_kernel(
    const float* __restrict__ x,  const float* __restrict__ nw0,
    const float* __restrict__ nb0, const float* __restrict__ nw1,
    const float* __restrict__ nw2)
{
    const int warp = threadIdx.x >> 5;
    const int lane = threadIdx.x & 31;
    const int row  = blockIdx.x * 8 + warp;
    const float* xr = x + (size_t)row * DIN;

    float4 v0 = ((const float4*)xr)[lane];
    float s = v0.x + v0.y + v0.z + v0.w;
    float q = v0.x*v0.x + v0.y*v0.y + v0.z*v0.z + v0.w*v0.w;
#pragma unroll
    for (int o = 16; o; o >>= 1) {
        s += __shfl_xor_sync(0xffffffffu, s, o);
        q += __shfl_xor_sync(0xffffffffu, q, o);
    }
    const float mu   = s * (1.0f / 128.0f);
    const float rstd = rsqrtf(q * (1.0f / 128.0f) - mu * mu + 1e-8f);

    float ss1 = 0.f, ss2 = 0.f;
    const float4* xr2 = (const float4*)(xr + 128);
#pragma unroll
    for (int j = lane; j < 88; j += 32) {
        float4 v = xr2[j];
        float d = v.x*v.x + v.y*v.y + v.z*v.z + v.w*v.w;
        if (j < 48) ss1 += d; else ss2 += d;
    }
#pragma unroll
    for (int o = 16; o; o >>= 1) {
        ss1 += __shfl_xor_sync(0xffffffffu, ss1, o);
        ss2 += __shfl_xor_sync(0xffffffffu, ss2, o);
    }
    const float inv = rsqrtf(0.5f * (ss1 * (1.f/192.f) + ss2 * (1.f/160.f)) + 1e-8f);

    const float invS0 = 0.08838834764831845f;
    float4 w = ((const float4*)nw0)[lane];
    float4 b = ((const float4*)nb0)[lane];
    __nv_bfloat16* y0 = gY0b + (size_t)row * 128 + lane * 4;
    y0[0] = __float2bfloat16(((v0.x - mu) * rstd * w.x + b.x) * invS0);
    y0[1] = __float2bfloat16(((v0.y - mu) * rstd * w.y + b.y) * invS0);
    y0[2] = __float2bfloat16(((v0.z - mu) * rstd * w.z + b.z) * invS0);
    y0[3] = __float2bfloat16(((v0.w - mu) * rstd * w.w + b.w) * invS0);

#pragma unroll
    for (int t = 0; t < 2; ++t) {
        int u = lane + t * 32;
        float c = inv * nw1[u] * 0.125f;
#pragma unroll
        for (int m = 0; m < 3; ++m)
            gY1b[((size_t)m * NROWS + row) * 64 + u] = __float2bfloat16(xr[128 + 3*u + m] * c);
    }
    {
        int u = lane;
        float c = inv * nw2[u] * 0.17677669529663689f;
#pragma unroll
        for (int m = 0; m < 5; ++m)
            gY2b[((size_t)m * NROWS + row) * 64 + u] =
                __float2bfloat16(xr[320 + 5*u + m] * c);
    }
}

// ================= HMMA GEMM body (persistent + cp.async pipeline) =========
// EPI 0: h0 -> silu/gate ; EPI 3: o0 with residual.
template<int KdA, int NT, int EPI>
__device__ __forceinline__ void mma_body(
    int t0, int tstr, int pb,
    const float* __restrict__ bias, const float* __restrict__ X,
    const float* __restrict__ alphap, float* __restrict__ Out)
{
    constexpr int NCH   = KdA / 64;
    constexpr int WT_N  = NT / 4;
    constexpr int NI    = WT_N / 8;
    constexpr int MI    = 4;
    constexpr int SAB   = 128 * 128;
    constexpr int SBB   = NT * 128;
    constexpr int STAGE = SAB + SBB;
    constexpr int DEPTH = 3;
    constexpr int NTILES = NROWS / 128;

    extern __shared__ __align__(16) char dsm[];
    const uint32_t sbase = smem_to_u32(dsm);

    const int tid  = threadIdx.x;
    const int lane = tid & 31;
    const int wid  = tid >> 5;
    const int wm   = wid >> 2;
    const int wn   = wid & 3;

    const __nv_bfloat16* gA  = (EPI == 0) ? gY0b : gSb;
    const __nv_bfloat16* gBw = (EPI == 0) ? gWt0 : gVt0;

    const int my_tiles = (t0 < NTILES) ? ((NTILES - 1 - t0) / tstr + 1) : 0;
    const int my_iters = my_tiles * NCH;

    auto issue_load = [&](int idx) {
        const int tile = t0 + (idx / NCH) * tstr;
        const int ch   = idx % NCH;
        const uint32_t st = sbase + (uint32_t)(idx % DEPTH) * STAGE;
        const __nv_bfloat16* Ab = gA + (size_t)(tile * 128) * KdA + ch * 64;
#pragma unroll
        for (int t = 0; t < 4; ++t) {
            int i2 = tid + t * 256;
            int r = i2 >> 3, v = i2 & 7;
            cp16(st + SWZ(r * 128 + v * 16), Ab + (size_t)r * KdA + v * 8);
        }
        const __nv_bfloat16* Bb = gBw + (size_t)pb * KdA + ch * 64;
#pragma unroll
        for (int t = 0; t < NT / 32; ++t) {
            int i2 = tid + t * 256;
            int r = i2 >> 3, v = i2 & 7;
            cp16(st + SAB + SWZ(r * 128 + v * 16), Bb + (size_t)r * KdA + v * 8);
        }
    };

    float acc[MI][NI][4];
#pragma unroll
    for (int i = 0; i < MI; ++i)
#pragma unroll
        for (int j = 0; j < NI; ++j)
#pragma unroll
            for (int r = 0; r < 4; ++r) acc[i][j][r] = 0.f;

    const int a_rowoff = (lane & 7) + ((lane >> 3) & 1) * 8;
    const int a_khalf  = lane >> 4;
    const int laneb    = lane & 15;
    const int b_rowoff = laneb & 7;
    const int b_khalf  = laneb >> 3;
    const float ta = (EPI == 3) ? tanhf(alphap[0]) : 0.0f;

#pragma unroll
    for (int i = 0; i < DEPTH; ++i) {
        if (i < my_iters) issue_load(i);
        cp_commit();
    }

#pragma unroll 1
    for (int it = 0; it < my_iters; ++it) {
        cp_wait2();
        __syncthreads();

        const uint32_t st = sbase + (uint32_t)(it % DEPTH) * STAGE;
#pragma unroll
        for (int ks = 0; ks < 4; ++ks) {
            const int kbyte = ks * 32;
            uint32_t af[MI][4], bf[NI][2];
#pragma unroll
            for (int mi = 0; mi < MI; ++mi) {
                int r = wm * 64 + mi * 16 + a_rowoff;
                ldsm_x4(af[mi], st + SWZ(r * 128 + kbyte + a_khalf * 16));
            }
#pragma unroll
            for (int ni = 0; ni < NI; ++ni) {
                int r = wn * WT_N + ni * 8 + b_rowoff;
                ldsm_x2(bf[ni], st + SAB + SWZ(r * 128 + kbyte + b_khalf * 16));
            }
#pragma unroll
            for (int mi = 0; mi < MI; ++mi)
#pragma unroll
                for (int ni = 0; ni < NI; ++ni)
                    mma16816(acc[mi][ni], af[mi], bf[ni]);
        }

        if ((it % NCH) == NCH - 1) {
            const int tile = t0 + (it / NCH) * tstr;
            const int rowBase = tile * 128;
#pragma unroll
            for (int mi = 0; mi < MI; ++mi) {
#pragma unroll
                for (int ni = 0; ni < NI; ++ni) {
                    const int p0 = pb + wn * WT_N + ni * 8 + (lane & 3) * 2;
#pragma unroll
                    for (int rp = 0; rp < 2; ++rp) {
                        const int row = rowBase + wm * 64 + mi * 16 + (lane >> 2) + rp * 8;
                        float v0 = acc[mi][ni][rp * 2];
                        float v1 = acc[mi][ni][rp * 2 + 1];
                        if (EPI == 0) {
                            float h0 = v0 + bias[p0];
                            float h1 = v1 + bias[p0 + 1];
                            if (p0 < H0D) {   // uniform per block
                                __nv_bfloat162 pk;
                                pk.x = __float2bfloat16(h0 * sigmf(h0) * 0.04419417382415922f);
                                pk.y = __float2bfloat16(h1 * sigmf(h1) * 0.04419417382415922f);
                                *(__nv_bfloat162*)(gSb + (size_t)row * 512 + p0) = pk;
                            } else {
                                // gate -> MMA-native layout for zo consumers
                                float2 pk = {sigmf(h0), sigmf(h1)};
                                int gcol = p0 - H0D;
                                int sg = gcol >> 6, pl = gcol & 63;
                                int lr = row & 127;
                                int wm_z = lr >> 6, mi_z = (lr >> 4) & 3,
                                    rp_z = (lr >> 3) & 1, lq = lr & 7;
                                int wn_z = pl >> 4, ni_z = (pl >> 3) & 1,
                                    l2 = (pl >> 1) & 3;
                                int wid_z = wm_z * 4 + wn_z;
                                int lane_z = lq * 4 + l2;
                                int idx = mi_z * 4 + ni_z * 2 + rp_z;
                                size_t off = (((size_t)sg * NTILES + tile) << 13)
                                           + wid_z * 1024 + (idx * 32 + lane_z) * 2;
                                *(float2*)(gG3 + off) = pk;
                            }
                        } else {
                            size_t o = (size_t)row * DIN + p0;
                            float2 xv = *(const float2*)(X + o);
                            float2 pk = {xv.x + ta * (v0 + bias[p0]),
                                         xv.y + ta * (v1 + bias[p0 + 1])};
                            *(float2*)(Out + o) = pk;
                        }
                        acc[mi][ni][rp * 2] = 0.f;
                        acc[mi][ni][rp * 2 + 1] = 0.f;
                    }
                }
            }
        }

        __syncthreads();
        if (it + DEPTH < my_iters) issue_load(it + DEPTH);
        cp_commit();
    }
}

__global__ void __launch_bounds__(256, 2) mma0_kernel(const float* __restrict__ bias) {
    mma_body<128, 128, 0>(blockIdx.x, gridDim.x, blockIdx.y * 128,
                          bias, nullptr, nullptr, nullptr);
}

// ================= fused z + down-projection body per spectral branch ======
template<int M, int BR>   // BR=1: H=256,K=64 ; BR=2: H=128,K=32
__device__ __forceinline__ void zo_body(int t0, int tstr)
{
    constexpr int NSLAB  = (BR == 1) ? 4 : 2;       // H / 64
    constexpr int KSY    = (BR == 1) ? 4 : 2;       // k16 steps of the z GEMM
    constexpr int OW     = (BR == 1) ? 64 : 32;     // o columns
    constexpr int ONI    = OW / 32;                 // 2 / 1
    constexpr int SGOF   = (BR == 1) ? 0 : 4;       // global gate-slab offset
    constexpr int WROWS  = (BR == 1) ? 256 : 128;
    constexpr int VROWS  = OW;
    constexpr int VCB    = VROWS * 128;             // bytes per Vt chunk
    constexpr int OFF_W  = 0;
    constexpr int OFF_V  = OFF_W + WROWS * 128;
    constexpr int OFF_Y  = OFF_V + NSLAB * VCB;
    constexpr int YB     = 128 * 128;
    constexpr int OFF_Z  = OFF_Y + 2 * YB;
    constexpr int NTILES = NROWS / 128;

    extern __shared__ __align__(16) char dsm[];
    const uint32_t sbase = smem_to_u32(dsm);

    const int tid  = threadIdx.x;
    const int wid  = tid >> 5;
    const int lane = tid & 31;
    const int wm   = wid >> 2;
    const int wn   = wid & 3;

    const __nv_bfloat16* gA  = (BR == 1) ? gY1b : gY2b;
    const __nv_bfloat16* gWt = (BR == 1) ? gWt1 : gWt2;
    const __nv_bfloat16* gVt = (BR == 1) ? gVt1 : gVt2;
    float* gO = (BR == 1) ? gO1 : gO2;
    const float SCALE = (BR == 1) ? 0.0625f : 0.08838834764831845f;

    const int my_tiles = (t0 < NTILES) ? ((NTILES - 1 - t0) / tstr + 1) : 0;
    const int my_iters = my_tiles * M;

    auto issue_y = [&](int j) {
        const int tile = t0 + (j / M) * tstr;
        const int mm   = j % M;
        const __nv_bfloat16* Ab = gA + ((size_t)mm * NROWS + tile * 128) * 64;
        const uint32_t yb = sbase + OFF_Y + (uint32_t)(j & 1) * YB;
        if (KSY == 4) {
#pragma unroll
            for (int t = 0; t < 4; ++t) {
                int i2 = tid + t * 256;
                int r = i2 >> 3, v = i2 & 7;
                cp16(yb + SWZ(r * 128 + v * 16), Ab + (size_t)r * 64 + v * 8);
            }
        } else {
#pragma unroll
            for (int t = 0; t < 2; ++t) {
                int i2 = tid + t * 256;
                int r = i2 >> 2, v = i2 & 3;
                cp16(yb + SWZ(r * 128 + v * 16), Ab + (size_t)r * 64 + v * 8);
            }
        }
    };

    // prologue: weights + Vt + Y(0) in group0, Y(1) in group1
    if (my_iters > 0) {
        if (BR == 1) {
#pragma unroll
            for (int t = 0; t < 8; ++t) {       // Wt1: 256 rows x 8 xfers
                int i2 = tid + t * 256;
                int r = i2 >> 3, v = i2 & 7;
                cp16(sbase + OFF_W + SWZ(r * 128 + v * 16), gWt + (size_t)r * 64 + v * 8);
            }
#pragma unroll
            for (int t = 0; t < 8; ++t) {       // Vt1: 4 chunks x 64 rows x 8 xfers
                int i2 = tid + t * 256;
                int s = i2 >> 9, p = (i2 >> 3) & 63, v = i2 & 7;
                cp16(sbase + OFF_V + s * VCB + SWZ(p * 128 + v * 16),
                     gVt + (size_t)p * 256 + s * 64 + v * 8);
            }
        } else {
#pragma unroll
            for (int t = 0; t < 2; ++t) {       // Wt2: 128 rows x 4 xfers (K=32)
                int i2 = tid + t * 256;
                int r = i2 >> 2, v = i2 & 3;
                cp16(sbase + OFF_W + SWZ(r * 128 + v * 16), gWt + (size_t)r * 64 + v * 8);
            }
#pragma unroll
            for (int t = 0; t < 2; ++t) {       // Vt2: 2 chunks x 32 rows x 8 xfers
                int i2 = tid + t * 256;
                int s = i2 >> 8, p = (i2 >> 3) & 31, v = i2 & 7;
                cp16(sbase + OFF_V + s * VCB + SWZ(p * 128 + v * 16),
                     gVt + (size_t)p * 128 + s * 64 + v * 8);
            }
        }
        issue_y(0);
    }
    cp_commit();
    if (1 < my_iters) issue_y(1);
    cp_commit();

    float oacc[4][ONI][4];
#pragma unroll
    for (int i = 0; i < 4; ++i)
#pragma unroll
        for (int j = 0; j < ONI; ++j)
#pragma unroll
            for (int r = 0; r < 4; ++r) oacc[i][j][r] = 0.f;

    const int a_rowoff = (lane & 7) + ((lane >> 3) & 1) * 8;
    const int a_khalf  = lane >> 4;
    const int laneb    = lane & 15;
    const int b_rowoff = laneb & 7;
    const int b_khalf  = laneb >> 3;

#pragma unroll 1
    for (int j = 0; j < my_iters; ++j) {
        cp_wait1();
        __syncthreads();

        const uint32_t yb = sbase + OFF_Y + (uint32_t)(j & 1) * YB;
        const int tile = t0 + (j / M) * tstr;
        const int rowBase = tile * 128;

#pragma unroll 1
        for (int s = 0; s < NSLAB; ++s) {
            const size_t gblk = ((size_t)(SGOF + s) * NTILES + tile) << 13;  // floats
            const float2* Gt = (const float2*)(gG3 + gblk) + wid * 512 + lane;
            prefetch_l1((const char*)(gG3 + gblk) + wid * 4096 + lane * 128);

            float zacc[4][2][4];
#pragma unroll
            for (int i = 0; i < 4; ++i)
#pragma unroll
                for (int n = 0; n < 2; ++n)
#pragma unroll
                    for (int r = 0; r < 4; ++r) zacc[i][n][r] = 0.f;

            // ---- z slab MMA ----
#pragma unroll
            for (int ks = 0; ks < KSY; ++ks) {
                const int kbyte = ks * 32;
                uint32_t af[4][4], bf[2][2];
#pragma unroll
                for (int mi = 0; mi < 4; ++mi) {
                    int r = wm * 64 + mi * 16 + a_rowoff;
                    ldsm_x4(af[mi], yb + SWZ(r * 128 + kbyte + a_khalf * 16));
                }
#pragma unroll
                for (int ni = 0; ni < 2; ++ni) {
                    int r = s * 64 + wn * 16 + ni * 8 + b_rowoff;
                    ldsm_x2(bf[ni], sbase + OFF_W + SWZ(r * 128 + kbyte + b_khalf * 16));
                }
#pragma unroll
                for (int mi = 0; mi < 4; ++mi)
#pragma unroll
                    for (int ni = 0; ni < 2; ++ni)
                        mma16816(zacc[mi][ni], af[mi], bf[ni]);
            }

            __syncthreads();
            // ---- gate + scale, stage bf16 z slab ----
#pragma unroll
            for (int mi = 0; mi < 4; ++mi) {
#pragma unroll
                for (int ni = 0; ni < 2; ++ni) {
                    const int pl = wn * 16 + ni * 8 + (lane & 3) * 2;
#pragma unroll
                    for (int rp = 0; rp < 2; ++rp) {
                        const int lrow = wm * 64 + mi * 16 + (lane >> 2) + rp * 8;
                        float2 g = Gt[(mi * 4 + ni * 2 + rp) * 32];
                        __nv_bfloat162 pk;
                        pk.x = __float2bfloat16(zacc[mi][ni][rp * 2]     * g.x * SCALE);
                        pk.y = __float2bfloat16(zacc[mi][ni][rp * 2 + 1] * g.y * SCALE);
                        *(uint32_t*)(dsm + OFF_Z + SWZ(lrow * 128 + pl * 2)) = *(uint32_t*)&pk;
                    }
                }
            }
            __syncthreads();

            // ---- o MMA: accumulate ----
#pragma unroll
            for (int ks2 = 0; ks2 < 4; ++ks2) {
                const int kbyte = ks2 * 32;
                uint32_t af2[4][4], bfo[ONI][2];
#pragma unroll
                for (int mi = 0; mi < 4; ++mi) {
                    int r = wm * 64 + mi * 16 + a_rowoff;
                    ldsm_x4(af2[mi], sbase + OFF_Z + SWZ(r * 128 + kbyte + a_khalf * 16));
                }
#pragma unroll
                for (int ni = 0; ni < ONI; ++ni) {
                    int rv = wn * (OW / 4) + ni * 8 + b_rowoff;
                    ldsm_x2(bfo[ni], sbase + OFF_V + s * VCB
                                     + SWZ(rv * 128 + kbyte + b_khalf * 16));
                }
#pragma unroll
                for (int mi = 0; mi < 4; ++mi)
#pragma unroll
                    for (int ni = 0; ni < ONI; ++ni)
                        mma16816(oacc[mi][ni], af2[mi], bfo[ni]);
            }
        }

        // ---- store o ----
        {
            const int mm = j % M;
#pragma unroll
            for (int mi = 0; mi < 4; ++mi) {
#pragma unroll
                for (int ni = 0; ni < ONI; ++ni) {
                    const int p0 = wn * (OW / 4) + ni * 8 + (lane & 3) * 2;
#pragma unroll
                    for (int rp = 0; rp < 2; ++rp) {
                        const int row = rowBase + wm * 64 + mi * 16 + (lane >> 2) + rp * 8;
                        float2 pk = {oacc[mi][ni][rp * 2], oacc[mi][ni][rp * 2 + 1]};
                        *(float2*)(gO + ((size_t)mm * NROWS + row) * OW + p0) = pk;
                        oacc[mi][ni][rp * 2] = 0.f;
                        oacc[mi][ni][rp * 2 + 1] = 0.f;
                    }
                }
            }
        }

        if (j + 2 < my_iters) issue_y(j + 2);
        cp_commit();
    }
}

// ================= fused tail: zo1 | zo2 | o0 in one launch =================
__global__ void __launch_bounds__(256, 2) tail_kernel(
    const float* __restrict__ c0, const float* __restrict__ X,
    const float* __restrict__ alphap, float* __restrict__ Out)
{
    const int phase = blockIdx.x / TAILG;
    const int bx    = blockIdx.x % TAILG;
    if (phase == 0)      zo_body<3, 1>(bx, TAILG);
    else if (phase == 1) zo_body<5, 2>(bx, TAILG);
    else                 mma_body<512, 128, 3>(bx, TAILG, 0, c0, X, alphap, Out);
}

// ================= final combine (smem transpose, coalesced) ================
__global__ void __launch_bounds__(256) combine_kernel(
    const float* __restrict__ x, const float* __restrict__ alphap,
    float* __restrict__ out)
{
    __shared__ float sO1[8][3][66];
    __shared__ float sO2[8][5][34];
    const int warp = threadIdx.x >> 5;
    const int lane = threadIdx.x & 31;
    const int row  = blockIdx.x * 8 + warp;
    const float ta = tanhf(alphap[0]);
    const float* xr = x + (size_t)row * DIN;
    float* outr = out + (size_t)row * DIN;

    // coalesced loads of this row's o1/o2 into smem
#pragma unroll
    for (int t = 0; t < 6; ++t) {          // 3*64 = 192 floats
        int idx = lane + t * 32;
        int m = idx >> 6, w = idx & 63;
        sO1[warp][m][w] = gO1[((size_t)m * NROWS + row) * 64 + w];
    }
#pragma unroll
    for (int t = 0; t < 5; ++t) {          // 5*32 = 160 floats
        int idx = lane + t * 32;
        int m = idx >> 5, w = idx & 31;
        sO2[warp][m][w] = gO2[((size_t)m * NROWS + row) * 32 + w];
    }
    __syncwarp();

#pragma unroll
    for (int t = 0; t < 6; ++t) {          // cols 128..319
        int c = 128 + lane + t * 32;
        int d = c - 128;
        outr[c] = xr[c] + ta * sO1[warp][d % 3][d / 3];
    }
#pragma unroll
    for (int t = 0; t < 5; ++t) {          // cols 320..479
        int c = 320 + lane + t * 32;
        int d = c - 320;
        outr[c] = xr[c] + ta * sO2[warp][d % 5][d / 5];
    }
}

// ================= launch =================
extern "C" void kernel_launch(void* const* d_in, const int* in_sizes, int n_in,
                              void* d_out, int out_size) {
    const float* x     = (const float*)d_in[0];
    const float* nw0   = (const float*)d_in[1];
    const float* nb0   = (const float*)d_in[2];
    const float* nw1   = (const float*)d_in[3];
    const float* nw2   = (const float*)d_in[4];
    const float* W0    = (const float*)d_in[5];
    const float* b0    = (const float*)d_in[6];
    const float* W1    = (const float*)d_in[7];
    const float* W2    = (const float*)d_in[8];
    const float* V0    = (const float*)d_in[9];
    const float* c0    = (const float*)d_in[10];
    const float* V1    = (const float*)d_in[11];
    const float* V2    = (const float*)d_in[12];
    const float* alpha = (const float*)d_in[13];
    float* out = (float*)d_out;

    constexpr int SM128 = 3 * (128 * 128 + 128 * 128);              // 96 KB
    constexpr int SMZ1  = 256*128 + 4*64*128 + 2*128*128 + 128*128; // 112 KB
    cudaFuncSetAttribute(mma0_kernel, cudaFuncAttributeMaxDynamicSharedMemorySize, SM128);
    cudaFuncSetAttribute(tail_kernel, cudaFuncAttributeMaxDynamicSharedMemorySize, SMZ1);

    convert_w<<<880, 256>>>(W0, W1, W2, V0, V1, V2);
    norm_kernel<<<NROWS / 8, 256>>>(x, nw0, nb0, nw1, nw2);

    // stage 1: h0 -> silu/gates
    mma0_kernel<<<dim3(84, 7, 1), 256, SM128>>>(b0);
    // fused tail: zo1 + zo2 + o0 (all depend only on h0/norm)
    tail_kernel<<<3 * TAILG, 256, SMZ1>>>(c0, x, alpha, out);
    // residual gather for cols 128..479
    combine_kernel<<<NROWS / 8, 256>>>(x, alpha, out);
}